// round 6
// baseline (speedup 1.0000x reference)
#include <cuda_runtime.h>
#include <cuda_bf16.h>
#include <cstdint>

#define NB 4
#define CH 512
#define HW 4096
#define NG 32
#define CPG 16
#define CHW ((long long)CH * HW)   // 2097152
#define SS  ((long long)HW * HW)   // 16777216

// smem geometry (uint32 units): 128 rows x (32 k + 16 pad) -> stride 48
// stride 48 (=16 mod 32): conflict-free LDS.128 frag loads and cp.async stores
#define SM_STRIDE 48
#define SM_OP     (128 * SM_STRIDE)       // 6144 u32 per operand
#define SM_STAGE  (2 * SM_OP)             // A + B per stage
#define SMEM_BYTES (2 * SM_STAGE * 4)     // 98304 B, double buffered

// Scratch (static device globals: allocation-free per harness rules)
static __device__ float g_ht[NB * CH * HW];                // H^T  [n][c]
static __device__ float g_q [NB * CH * HW];                // Q^T  [n][c]
static __device__ float g_k [NB * CH * HW];                // K^T  [m][c]
static __device__ float g_v [NB * CH * HW];                // V    [c][m]
static __device__ float g_o [NB * CH * HW];                // O^T  [n][c]
static __device__ float g_s [(size_t)NB * HW * HW];        // S    [n][m]

// ---------------------------------------------------------------------------
// helpers
// ---------------------------------------------------------------------------
__device__ __forceinline__ void mma8(float* c, uint32_t a0, uint32_t a1,
                                     uint32_t a2, uint32_t a3,
                                     uint32_t b0, uint32_t b1) {
    asm volatile(
        "mma.sync.aligned.m16n8k8.row.col.f32.tf32.tf32.f32 "
        "{%0,%1,%2,%3}, {%4,%5,%6,%7}, {%8,%9}, {%0,%1,%2,%3};"
        : "+f"(c[0]), "+f"(c[1]), "+f"(c[2]), "+f"(c[3])
        : "r"(a0), "r"(a1), "r"(a2), "r"(a3), "r"(b0), "r"(b1));
}

__device__ __forceinline__ void cpasync16(uint32_t dst, const void* src) {
    asm volatile("cp.async.cg.shared.global [%0], [%1], 16;" :: "r"(dst), "l"(src));
}

__device__ __forceinline__ uint32_t smem_u32(const void* p) {
    uint32_t a;
    asm("{ .reg .u64 t; cvta.to.shared.u64 t, %1; cvt.u32.u64 %0, t; }" : "=r"(a) : "l"(p));
    return a;
}

// ---------------------------------------------------------------------------
// GroupNorm -> transposed output H^T[n][c].
// ---------------------------------------------------------------------------
__global__ __launch_bounds__(512) void groupnorm_t_kernel(
    const float* __restrict__ x, const float* __restrict__ gamma,
    const float* __restrict__ beta, float* __restrict__ ht)
{
    int b = blockIdx.x / NG, grp = blockIdx.x % NG;
    size_t base = ((size_t)b * CH + (size_t)grp * CPG) * HW;
    const float4* x4 = (const float4*)(x + base);
    const int n4 = CPG * HW / 4;  // 16384

    float s = 0.f, ss = 0.f;
    for (int i = threadIdx.x; i < n4; i += blockDim.x) {
        float4 v = x4[i];
        s  += v.x + v.y + v.z + v.w;
        ss += v.x * v.x + v.y * v.y + v.z * v.z + v.w * v.w;
    }
    __shared__ float shs[16], shss[16];
#pragma unroll
    for (int o = 16; o > 0; o >>= 1) {
        s  += __shfl_xor_sync(0xffffffffu, s, o);
        ss += __shfl_xor_sync(0xffffffffu, ss, o);
    }
    int wid = threadIdx.x >> 5, lid = threadIdx.x & 31;
    if (lid == 0) { shs[wid] = s; shss[wid] = ss; }
    __syncthreads();
    if (threadIdx.x == 0) {
        float ts = 0.f, tss = 0.f;
#pragma unroll
        for (int w = 0; w < 16; w++) { ts += shs[w]; tss += shss[w]; }
        shs[0] = ts; shss[0] = tss;
    }
    __syncthreads();
    const float invn = 1.f / (float)(CPG * HW);
    float mean = shs[0] * invn;
    float var  = shss[0] * invn - mean * mean;
    float rstd = rsqrtf(var + 1e-5f);

    int ch  = threadIdx.x >> 5;        // 0..15
    int nl  = threadIdx.x & 31;        // 0..31
    float ga = gamma[grp * CPG + ch] * rstd;
    float be = beta [grp * CPG + ch] - mean * ga;

    __shared__ float sm[16 * 132];
    float* htp = ht + (size_t)b * CHW;

    for (int tile = 0; tile < HW / 128; tile++) {
        float4 v = x4[ch * (HW / 4) + tile * 32 + nl];
        v.x = v.x * ga + be; v.y = v.y * ga + be;
        v.z = v.z * ga + be; v.w = v.w * ga + be;
        *(float4*)&sm[ch * 132 + nl * 4] = v;
        __syncthreads();
        int i  = threadIdx.x >> 2;     // 0..127
        int c4 = threadIdx.x & 3;      // 0..3
        float4 w;
        w.x = sm[(c4 * 4 + 0) * 132 + i];
        w.y = sm[(c4 * 4 + 1) * 132 + i];
        w.z = sm[(c4 * 4 + 2) * 132 + i];
        w.w = sm[(c4 * 4 + 3) * 132 + i];
        *(float4*)(htp + (size_t)(tile * 128 + i) * CH + grp * CPG + c4 * 4) = w;
        __syncthreads();
    }
}

// ---------------------------------------------------------------------------
// Unified tf32 mma GEMM, cp.async double-buffered, LDS.128 fragment loads.
//   C[m][n] = sum_k A[m][k] * B[n][k]   (both operands k-contiguous)
//   128x128 tile, BK=32, 256 threads (8 warps, 64x32 warp tiles).
//   kk-pair permutation: thread t's k-columns for two adjacent kk-steps sit
//   at contiguous addrs kc..kc+3 (kc = 16*w2 + 4t); identical for A and B,
//   so the MMA result is invariant while frag loads become 16B-vectorized.
// ---------------------------------------------------------------------------
template<bool TRANS, bool HASBIAS, bool HASRESID>
__global__ __launch_bounds__(256, 2) void mma_gemm(
    const float* __restrict__ A, int ldA, long long aStride,
    const float* __restrict__ B, int ldB, long long bStride,
    float* __restrict__ C, int ldC, long long cStride,
    const float* __restrict__ bias,
    const float* __restrict__ resid, long long rStride,
    int K, float scale)
{
    extern __shared__ uint32_t sm[];
    const uint32_t smb = smem_u32(sm);

    const int tid  = threadIdx.x;
    const int lane = tid & 31;
    const int wid  = tid >> 5;
    const int g    = lane >> 2;       // 0..7
    const int t    = lane & 3;        // 0..3
    const int warpM = (wid >> 2) * 64;
    const int warpN = (wid & 3) * 32;

    const int m0 = blockIdx.y * 128, n0 = blockIdx.x * 128;
    const float* Ap = A + blockIdx.z * aStride;
    const float* Bp = B + blockIdx.z * bStride;

    // loader mapping: thread covers rows r0 + {0,32,64,96}, fixed 16B col kq
    const int r0 = tid >> 3;          // 0..31
    const int kq = tid & 7;           // float4 col within BK=32

    float acc[4][4][4] = {};

    auto load_stage = [&](int st, int k0) {
        uint32_t dA = smb + (uint32_t)(st * SM_STAGE + r0 * SM_STRIDE + kq * 4) * 4;
        uint32_t dB = dA + SM_OP * 4;
        const float* sA = Ap + (size_t)(m0 + r0) * ldA + k0 + kq * 4;
        const float* sB = Bp + (size_t)(n0 + r0) * ldB + k0 + kq * 4;
#pragma unroll
        for (int i = 0; i < 4; i++) {
            cpasync16(dA + (uint32_t)(32 * i * SM_STRIDE) * 4, sA + (size_t)(32 * i) * ldA);
            cpasync16(dB + (uint32_t)(32 * i * SM_STRIDE) * 4, sB + (size_t)(32 * i) * ldB);
        }
    };

    load_stage(0, 0);
    asm volatile("cp.async.commit_group;");

    int s = 0;
    for (int k0 = 0; k0 < K; k0 += 32, s ^= 1) {
        if (k0 + 32 < K) {
            load_stage(s ^ 1, k0 + 32);
            asm volatile("cp.async.commit_group;");
            asm volatile("cp.async.wait_group 1;");
        } else {
            asm volatile("cp.async.wait_group 0;");
        }
        __syncthreads();

        const uint32_t* As = sm + s * SM_STAGE;
        const uint32_t* Bs = As + SM_OP;
#pragma unroll
        for (int w2 = 0; w2 < 2; w2++) {          // kk-pair (covers kk=2w2, 2w2+1)
            const int kc = w2 * 16 + 4 * t;
            uint4 bfv[4];
#pragma unroll
            for (int nt = 0; nt < 4; nt++)
                bfv[nt] = *(const uint4*)&Bs[(warpN + nt * 8 + g) * SM_STRIDE + kc];
#pragma unroll
            for (int mt = 0; mt < 4; mt++) {
                int r = warpM + mt * 16 + g;
                uint4 lo = *(const uint4*)&As[(r)     * SM_STRIDE + kc];
                uint4 hi = *(const uint4*)&As[(r + 8) * SM_STRIDE + kc];
                // even kk: cols kc,kc+1
#pragma unroll
                for (int nt = 0; nt < 4; nt++)
                    mma8(acc[mt][nt], lo.x, hi.x, lo.y, hi.y, bfv[nt].x, bfv[nt].y);
                // odd kk: cols kc+2,kc+3
#pragma unroll
                for (int nt = 0; nt < 4; nt++)
                    mma8(acc[mt][nt], lo.z, hi.z, lo.w, hi.w, bfv[nt].z, bfv[nt].w);
            }
        }
        __syncthreads();
    }

    // epilogue
    float* Cp = C + blockIdx.z * cStride;
    const float* Rp = HASRESID ? (resid + blockIdx.z * rStride) : nullptr;
#pragma unroll
    for (int mt = 0; mt < 4; mt++) {
        int row = m0 + warpM + mt * 16 + g;
        float b0 = 0.f, b1 = 0.f;
        if (HASBIAS) { b0 = bias[row]; b1 = bias[row + 8]; }
#pragma unroll
        for (int nt = 0; nt < 4; nt++) {
            int col = n0 + warpN + nt * 8 + 2 * t;
            float v0 = acc[mt][nt][0] * scale + b0;
            float v1 = acc[mt][nt][1] * scale + b0;
            float v2 = acc[mt][nt][2] * scale + b1;
            float v3 = acc[mt][nt][3] * scale + b1;
            if (TRANS) {
                Cp[(size_t)(col)     * ldC + row    ] = v0;
                Cp[(size_t)(col + 1) * ldC + row    ] = v1;
                Cp[(size_t)(col)     * ldC + row + 8] = v2;
                Cp[(size_t)(col + 1) * ldC + row + 8] = v3;
            } else {
                if (HASRESID) {
                    float2 r0v = *(const float2*)(Rp + (size_t)row * ldC + col);
                    float2 r1v = *(const float2*)(Rp + (size_t)(row + 8) * ldC + col);
                    v0 += r0v.x; v1 += r0v.y; v2 += r1v.x; v3 += r1v.y;
                }
                *(float2*)(Cp + (size_t)row * ldC + col)       = make_float2(v0, v1);
                *(float2*)(Cp + (size_t)(row + 8) * ldC + col) = make_float2(v2, v3);
            }
        }
    }
}

// ---------------------------------------------------------------------------
// Row softmax in place over last dim (4096). One block per row.
// ---------------------------------------------------------------------------
__global__ __launch_bounds__(256) void softmax_kernel(float* __restrict__ S)
{
    float4* p4 = (float4*)(S + (size_t)blockIdx.x * HW);
    int tid = threadIdx.x;
    float4 r[4];
    float mx = -3.0e38f;
#pragma unroll
    for (int i = 0; i < 4; i++) {
        r[i] = p4[tid + i * 256];
        mx = fmaxf(mx, fmaxf(fmaxf(r[i].x, r[i].y), fmaxf(r[i].z, r[i].w)));
    }
    __shared__ float red[8];
#pragma unroll
    for (int o = 16; o > 0; o >>= 1) mx = fmaxf(mx, __shfl_xor_sync(0xffffffffu, mx, o));
    if ((tid & 31) == 0) red[tid >> 5] = mx;
    __syncthreads();
    mx = red[0];
#pragma unroll
    for (int w = 1; w < 8; w++) mx = fmaxf(mx, red[w]);

    float sum = 0.f;
#pragma unroll
    for (int i = 0; i < 4; i++) {
        r[i].x = __expf(r[i].x - mx); r[i].y = __expf(r[i].y - mx);
        r[i].z = __expf(r[i].z - mx); r[i].w = __expf(r[i].w - mx);
        sum += r[i].x + r[i].y + r[i].z + r[i].w;
    }
#pragma unroll
    for (int o = 16; o > 0; o >>= 1) sum += __shfl_xor_sync(0xffffffffu, sum, o);
    __syncthreads();
    if ((tid & 31) == 0) red[tid >> 5] = sum;
    __syncthreads();
    sum = 0.f;
#pragma unroll
    for (int w = 0; w < 8; w++) sum += red[w];
    float inv = 1.f / sum;
#pragma unroll
    for (int i = 0; i < 4; i++) {
        r[i].x *= inv; r[i].y *= inv; r[i].z *= inv; r[i].w *= inv;
        p4[tid + i * 256] = r[i];
    }
}

// ---------------------------------------------------------------------------
extern "C" void kernel_launch(void* const* d_in, const int* in_sizes, int n_in,
                              void* d_out, int out_size)
{
    const float* x     = (const float*)d_in[0];
    const float* gamma = (const float*)d_in[1];
    const float* beta  = (const float*)d_in[2];
    const float* wq    = (const float*)d_in[3];
    const float* bq    = (const float*)d_in[4];
    const float* wk    = (const float*)d_in[5];
    const float* bk    = (const float*)d_in[6];
    const float* wv    = (const float*)d_in[7];
    const float* bv    = (const float*)d_in[8];
    const float* wo    = (const float*)d_in[9];
    const float* bo    = (const float*)d_in[10];
    float* out = (float*)d_out;

    float *pht, *pq, *pk, *pv, *po, *ps;
    cudaGetSymbolAddress((void**)&pht, g_ht);
    cudaGetSymbolAddress((void**)&pq,  g_q);
    cudaGetSymbolAddress((void**)&pk,  g_k);
    cudaGetSymbolAddress((void**)&pv,  g_v);
    cudaGetSymbolAddress((void**)&po,  g_o);
    cudaGetSymbolAddress((void**)&ps,  g_s);

    cudaFuncSetAttribute(mma_gemm<true,  true,  false>, cudaFuncAttributeMaxDynamicSharedMemorySize, SMEM_BYTES);
    cudaFuncSetAttribute(mma_gemm<false, true,  false>, cudaFuncAttributeMaxDynamicSharedMemorySize, SMEM_BYTES);
    cudaFuncSetAttribute(mma_gemm<false, false, false>, cudaFuncAttributeMaxDynamicSharedMemorySize, SMEM_BYTES);
    cudaFuncSetAttribute(mma_gemm<true,  false, false>, cudaFuncAttributeMaxDynamicSharedMemorySize, SMEM_BYTES);
    cudaFuncSetAttribute(mma_gemm<false, true,  true >, cudaFuncAttributeMaxDynamicSharedMemorySize, SMEM_BYTES);

    // GroupNorm -> H^T[n][c]
    groupnorm_t_kernel<<<NB * NG, 512>>>(x, gamma, beta, pht);

    dim3 gP(HW / 128, CH / 128, NB);   // proj GEMMs: M=512, N=4096
    dim3 gS(HW / 128, HW / 128, NB);   // scores: M=N=4096

    // Q^T = (Wq . H)^T, transposed epilogue
    mma_gemm<true, true, false><<<gP, 256, SMEM_BYTES>>>(wq, CH, 0, pht, CH, CHW,
                                             pq, CH, CHW, bq, nullptr, 0, CH, 1.f);
    // K^T
    mma_gemm<true, true, false><<<gP, 256, SMEM_BYTES>>>(wk, CH, 0, pht, CH, CHW,
                                             pk, CH, CHW, bk, nullptr, 0, CH, 1.f);
    // V natural [d][n]
    mma_gemm<false, true, false><<<gP, 256, SMEM_BYTES>>>(wv, CH, 0, pht, CH, CHW,
                                              pv, HW, CHW, bv, nullptr, 0, CH, 1.f);
    // S[n][m] = scale * Q . K^T
    mma_gemm<false, false, false><<<gS, 256, SMEM_BYTES>>>(pq, CH, CHW, pk, CH, CHW,
                                               ps, HW, SS, nullptr, nullptr, 0,
                                               CH, 0.04419417382415922f);
    softmax_kernel<<<NB * HW, 256>>>(ps);

    // O^T[n][c]: A = V[c][m], B = attn[n][m], k = m; transposed write
    mma_gemm<true, false, false><<<gP, 256, SMEM_BYTES>>>(pv, HW, CHW, ps, HW, SS,
                                              po, CH, CHW, nullptr, nullptr, 0, HW, 1.f);
    // out[d][n] = Wo . O + bo + x
    mma_gemm<false, true, true><<<gP, 256, SMEM_BYTES>>>(wo, CH, 0, po, CH, CHW,
                                             out, HW, CHW, bo, x, CHW, CH, 1.f);
}

// round 7
// speedup vs baseline: 1.3903x; 1.3903x over previous
#include <cuda_runtime.h>
#include <cuda_bf16.h>
#include <cstdint>

#define NB 4
#define CH 512
#define HW 4096
#define NG 32
#define CPG 16
#define CHW ((long long)CH * HW)   // 2097152
#define SS  ((long long)HW * HW)   // 16777216

// smem geometry (uint32 units): 128 rows x (32 k + 8 pad) -> stride 40
// stride 40 => conflict-free LDS.64 frag loads (banks 8g+2t) and cp.async stores
#define SM_STRIDE 40
#define SM_OP     (128 * SM_STRIDE)       // 5120 u32 per operand
#define SM_STAGE  (2 * SM_OP)             // A + B per stage
#define SMEM_BYTES (2 * SM_STAGE * 4)     // 81920 B, double buffered

// Scratch (static device globals: allocation-free per harness rules)
static __device__ float g_ht[NB * CH * HW];                // H^T  [n][c]
static __device__ float g_q [NB * CH * HW];                // Q^T  [n][c]
static __device__ float g_k [NB * CH * HW];                // K^T  [m][c]
static __device__ float g_v [NB * CH * HW];                // V    [c][m]
static __device__ float g_o [NB * CH * HW];                // O^T  [n][c]
static __device__ float g_s [(size_t)NB * HW * HW];        // S    [n][m]

// ---------------------------------------------------------------------------
// helpers
// ---------------------------------------------------------------------------
__device__ __forceinline__ void mma8(float* c, uint32_t a0, uint32_t a1,
                                     uint32_t a2, uint32_t a3,
                                     uint32_t b0, uint32_t b1) {
    asm volatile(
        "mma.sync.aligned.m16n8k8.row.col.f32.tf32.tf32.f32 "
        "{%0,%1,%2,%3}, {%4,%5,%6,%7}, {%8,%9}, {%0,%1,%2,%3};"
        : "+f"(c[0]), "+f"(c[1]), "+f"(c[2]), "+f"(c[3])
        : "r"(a0), "r"(a1), "r"(a2), "r"(a3), "r"(b0), "r"(b1));
}

__device__ __forceinline__ void cpasync16(uint32_t dst, const void* src) {
    asm volatile("cp.async.cg.shared.global [%0], [%1], 16;" :: "r"(dst), "l"(src));
}

__device__ __forceinline__ uint32_t smem_u32(const void* p) {
    uint32_t a;
    asm("{ .reg .u64 t; cvta.to.shared.u64 t, %1; cvt.u32.u64 %0, t; }" : "=r"(a) : "l"(p));
    return a;
}

// ---------------------------------------------------------------------------
// GroupNorm -> transposed output H^T[n][c].
// ---------------------------------------------------------------------------
__global__ __launch_bounds__(512) void groupnorm_t_kernel(
    const float* __restrict__ x, const float* __restrict__ gamma,
    const float* __restrict__ beta, float* __restrict__ ht)
{
    int b = blockIdx.x / NG, grp = blockIdx.x % NG;
    size_t base = ((size_t)b * CH + (size_t)grp * CPG) * HW;
    const float4* x4 = (const float4*)(x + base);
    const int n4 = CPG * HW / 4;  // 16384

    float s = 0.f, ss = 0.f;
    for (int i = threadIdx.x; i < n4; i += blockDim.x) {
        float4 v = x4[i];
        s  += v.x + v.y + v.z + v.w;
        ss += v.x * v.x + v.y * v.y + v.z * v.z + v.w * v.w;
    }
    __shared__ float shs[16], shss[16];
#pragma unroll
    for (int o = 16; o > 0; o >>= 1) {
        s  += __shfl_xor_sync(0xffffffffu, s, o);
        ss += __shfl_xor_sync(0xffffffffu, ss, o);
    }
    int wid = threadIdx.x >> 5, lid = threadIdx.x & 31;
    if (lid == 0) { shs[wid] = s; shss[wid] = ss; }
    __syncthreads();
    if (threadIdx.x == 0) {
        float ts = 0.f, tss = 0.f;
#pragma unroll
        for (int w = 0; w < 16; w++) { ts += shs[w]; tss += shss[w]; }
        shs[0] = ts; shss[0] = tss;
    }
    __syncthreads();
    const float invn = 1.f / (float)(CPG * HW);
    float mean = shs[0] * invn;
    float var  = shss[0] * invn - mean * mean;
    float rstd = rsqrtf(var + 1e-5f);

    int ch  = threadIdx.x >> 5;        // 0..15
    int nl  = threadIdx.x & 31;        // 0..31
    float ga = gamma[grp * CPG + ch] * rstd;
    float be = beta [grp * CPG + ch] - mean * ga;

    __shared__ float sm[16 * 132];
    float* htp = ht + (size_t)b * CHW;

    for (int tile = 0; tile < HW / 128; tile++) {
        float4 v = x4[ch * (HW / 4) + tile * 32 + nl];
        v.x = v.x * ga + be; v.y = v.y * ga + be;
        v.z = v.z * ga + be; v.w = v.w * ga + be;
        *(float4*)&sm[ch * 132 + nl * 4] = v;
        __syncthreads();
        int i  = threadIdx.x >> 2;     // 0..127
        int c4 = threadIdx.x & 3;      // 0..3
        float4 w;
        w.x = sm[(c4 * 4 + 0) * 132 + i];
        w.y = sm[(c4 * 4 + 1) * 132 + i];
        w.z = sm[(c4 * 4 + 2) * 132 + i];
        w.w = sm[(c4 * 4 + 3) * 132 + i];
        *(float4*)(htp + (size_t)(tile * 128 + i) * CH + grp * CPG + c4 * 4) = w;
        __syncthreads();
    }
}

// ---------------------------------------------------------------------------
// Unified tf32 mma GEMM, cp.async double-buffered, LDS.64 fragment loads.
//   C[m][n] = sum_k A[m][k] * B[n][k]   (both operands k-contiguous)
//   128x128 tile, BK=32, 512 threads (16 warps, 4x4 grid of 32x32 warp tiles).
//   k-permutation: logical klo(t)=kb+2t, khi(t)=kb+2t+1, same for A & B ->
//   MMA-invariant; enables 8B-vectorized fragment loads.
// ---------------------------------------------------------------------------
template<bool TRANS, bool HASBIAS, bool HASRESID>
__global__ __launch_bounds__(512, 2) void mma_gemm(
    const float* __restrict__ A, int ldA, long long aStride,
    const float* __restrict__ B, int ldB, long long bStride,
    float* __restrict__ C, int ldC, long long cStride,
    const float* __restrict__ bias,
    const float* __restrict__ resid, long long rStride,
    int K, float scale)
{
    extern __shared__ uint32_t sm[];
    const uint32_t smb = smem_u32(sm);

    const int tid  = threadIdx.x;
    const int lane = tid & 31;
    const int wid  = tid >> 5;        // 0..15
    const int g    = lane >> 2;       // 0..7
    const int t    = lane & 3;        // 0..3
    const int warpM = (wid >> 2) * 32;    // 4 m-groups
    const int warpN = (wid & 3) * 32;     // 4 n-groups

    const int m0 = blockIdx.y * 128, n0 = blockIdx.x * 128;
    const float* Ap = A + blockIdx.z * aStride;
    const float* Bp = B + blockIdx.z * bStride;

    // loader: thread covers rows r0 and r0+64, fixed 16B col kq
    const int r0 = tid >> 3;          // 0..63
    const int kq = tid & 7;           // float4 col within BK=32

    float acc[2][4][4] = {};

    auto load_stage = [&](int st, int k0) {
        uint32_t dA = smb + (uint32_t)(st * SM_STAGE + r0 * SM_STRIDE + kq * 4) * 4;
        uint32_t dB = dA + SM_OP * 4;
        const float* sA = Ap + (size_t)(m0 + r0) * ldA + k0 + kq * 4;
        const float* sB = Bp + (size_t)(n0 + r0) * ldB + k0 + kq * 4;
#pragma unroll
        for (int i = 0; i < 2; i++) {
            cpasync16(dA + (uint32_t)(64 * i * SM_STRIDE) * 4, sA + (size_t)(64 * i) * ldA);
            cpasync16(dB + (uint32_t)(64 * i * SM_STRIDE) * 4, sB + (size_t)(64 * i) * ldB);
        }
    };

    load_stage(0, 0);
    asm volatile("cp.async.commit_group;");

    int s = 0;
    for (int k0 = 0; k0 < K; k0 += 32, s ^= 1) {
        if (k0 + 32 < K) {
            load_stage(s ^ 1, k0 + 32);
            asm volatile("cp.async.commit_group;");
            asm volatile("cp.async.wait_group 1;");
        } else {
            asm volatile("cp.async.wait_group 0;");
        }
        __syncthreads();

        const uint32_t* As = sm + s * SM_STAGE;
        const uint32_t* Bs = As + SM_OP;
#pragma unroll
        for (int kk = 0; kk < 4; kk++) {
            const int kc = kk * 8 + 2 * t;       // klo column; khi = kc+1
            uint32_t af[2][4], bf[4][2];
#pragma unroll
            for (int mt = 0; mt < 2; mt++) {
                int r = warpM + mt * 16 + g;
                uint2 lo = *(const uint2*)&As[(r)     * SM_STRIDE + kc];
                uint2 hi = *(const uint2*)&As[(r + 8) * SM_STRIDE + kc];
                af[mt][0] = lo.x; af[mt][1] = hi.x;
                af[mt][2] = lo.y; af[mt][3] = hi.y;
            }
#pragma unroll
            for (int nt = 0; nt < 4; nt++) {
                int r = warpN + nt * 8 + g;
                uint2 bb = *(const uint2*)&Bs[r * SM_STRIDE + kc];
                bf[nt][0] = bb.x; bf[nt][1] = bb.y;
            }
#pragma unroll
            for (int mt = 0; mt < 2; mt++)
#pragma unroll
                for (int nt = 0; nt < 4; nt++)
                    mma8(acc[mt][nt], af[mt][0], af[mt][1], af[mt][2], af[mt][3],
                         bf[nt][0], bf[nt][1]);
        }
        __syncthreads();
    }

    // epilogue
    float* Cp = C + blockIdx.z * cStride;
    const float* Rp = HASRESID ? (resid + blockIdx.z * rStride) : nullptr;
#pragma unroll
    for (int mt = 0; mt < 2; mt++) {
        int row = m0 + warpM + mt * 16 + g;
        float b0 = 0.f, b1 = 0.f;
        if (HASBIAS) { b0 = bias[row]; b1 = bias[row + 8]; }
#pragma unroll
        for (int nt = 0; nt < 4; nt++) {
            int col = n0 + warpN + nt * 8 + 2 * t;
            float v0 = acc[mt][nt][0] * scale + b0;
            float v1 = acc[mt][nt][1] * scale + b0;
            float v2 = acc[mt][nt][2] * scale + b1;
            float v3 = acc[mt][nt][3] * scale + b1;
            if (TRANS) {
                Cp[(size_t)(col)     * ldC + row    ] = v0;
                Cp[(size_t)(col + 1) * ldC + row    ] = v1;
                Cp[(size_t)(col)     * ldC + row + 8] = v2;
                Cp[(size_t)(col + 1) * ldC + row + 8] = v3;
            } else {
                if (HASRESID) {
                    float2 r0v = *(const float2*)(Rp + (size_t)row * ldC + col);
                    float2 r1v = *(const float2*)(Rp + (size_t)(row + 8) * ldC + col);
                    v0 += r0v.x; v1 += r0v.y; v2 += r1v.x; v3 += r1v.y;
                }
                *(float2*)(Cp + (size_t)row * ldC + col)       = make_float2(v0, v1);
                *(float2*)(Cp + (size_t)(row + 8) * ldC + col) = make_float2(v2, v3);
            }
        }
    }
}

// ---------------------------------------------------------------------------
// Row softmax in place over last dim (4096). One block per row.
// ---------------------------------------------------------------------------
__global__ __launch_bounds__(256) void softmax_kernel(float* __restrict__ S)
{
    float4* p4 = (float4*)(S + (size_t)blockIdx.x * HW);
    int tid = threadIdx.x;
    float4 r[4];
    float mx = -3.0e38f;
#pragma unroll
    for (int i = 0; i < 4; i++) {
        r[i] = p4[tid + i * 256];
        mx = fmaxf(mx, fmaxf(fmaxf(r[i].x, r[i].y), fmaxf(r[i].z, r[i].w)));
    }
    __shared__ float red[8];
#pragma unroll
    for (int o = 16; o > 0; o >>= 1) mx = fmaxf(mx, __shfl_xor_sync(0xffffffffu, mx, o));
    if ((tid & 31) == 0) red[tid >> 5] = mx;
    __syncthreads();
    mx = red[0];
#pragma unroll
    for (int w = 1; w < 8; w++) mx = fmaxf(mx, red[w]);

    float sum = 0.f;
#pragma unroll
    for (int i = 0; i < 4; i++) {
        r[i].x = __expf(r[i].x - mx); r[i].y = __expf(r[i].y - mx);
        r[i].z = __expf(r[i].z - mx); r[i].w = __expf(r[i].w - mx);
        sum += r[i].x + r[i].y + r[i].z + r[i].w;
    }
#pragma unroll
    for (int o = 16; o > 0; o >>= 1) sum += __shfl_xor_sync(0xffffffffu, sum, o);
    __syncthreads();
    if ((tid & 31) == 0) red[tid >> 5] = sum;
    __syncthreads();
    sum = 0.f;
#pragma unroll
    for (int w = 0; w < 8; w++) sum += red[w];
    float inv = 1.f / sum;
#pragma unroll
    for (int i = 0; i < 4; i++) {
        r[i].x *= inv; r[i].y *= inv; r[i].z *= inv; r[i].w *= inv;
        p4[tid + i * 256] = r[i];
    }
}

// ---------------------------------------------------------------------------
extern "C" void kernel_launch(void* const* d_in, const int* in_sizes, int n_in,
                              void* d_out, int out_size)
{
    const float* x     = (const float*)d_in[0];
    const float* gamma = (const float*)d_in[1];
    const float* beta  = (const float*)d_in[2];
    const float* wq    = (const float*)d_in[3];
    const float* bq    = (const float*)d_in[4];
    const float* wk    = (const float*)d_in[5];
    const float* bk    = (const float*)d_in[6];
    const float* wv    = (const float*)d_in[7];
    const float* bv    = (const float*)d_in[8];
    const float* wo    = (const float*)d_in[9];
    const float* bo    = (const float*)d_in[10];
    float* out = (float*)d_out;

    float *pht, *pq, *pk, *pv, *po, *ps;
    cudaGetSymbolAddress((void**)&pht, g_ht);
    cudaGetSymbolAddress((void**)&pq,  g_q);
    cudaGetSymbolAddress((void**)&pk,  g_k);
    cudaGetSymbolAddress((void**)&pv,  g_v);
    cudaGetSymbolAddress((void**)&po,  g_o);
    cudaGetSymbolAddress((void**)&ps,  g_s);

    cudaFuncSetAttribute(mma_gemm<true,  true,  false>, cudaFuncAttributeMaxDynamicSharedMemorySize, SMEM_BYTES);
    cudaFuncSetAttribute(mma_gemm<false, true,  false>, cudaFuncAttributeMaxDynamicSharedMemorySize, SMEM_BYTES);
    cudaFuncSetAttribute(mma_gemm<false, false, false>, cudaFuncAttributeMaxDynamicSharedMemorySize, SMEM_BYTES);
    cudaFuncSetAttribute(mma_gemm<true,  false, false>, cudaFuncAttributeMaxDynamicSharedMemorySize, SMEM_BYTES);
    cudaFuncSetAttribute(mma_gemm<false, true,  true >, cudaFuncAttributeMaxDynamicSharedMemorySize, SMEM_BYTES);

    // GroupNorm -> H^T[n][c]
    groupnorm_t_kernel<<<NB * NG, 512>>>(x, gamma, beta, pht);

    dim3 gP(HW / 128, CH / 128, NB);   // proj GEMMs: M=512, N=4096
    dim3 gS(HW / 128, HW / 128, NB);   // scores: M=N=4096

    // Q^T = (Wq . H)^T, transposed epilogue
    mma_gemm<true, true, false><<<gP, 512, SMEM_BYTES>>>(wq, CH, 0, pht, CH, CHW,
                                             pq, CH, CHW, bq, nullptr, 0, CH, 1.f);
    // K^T
    mma_gemm<true, true, false><<<gP, 512, SMEM_BYTES>>>(wk, CH, 0, pht, CH, CHW,
                                             pk, CH, CHW, bk, nullptr, 0, CH, 1.f);
    // V natural [d][n]
    mma_gemm<false, true, false><<<gP, 512, SMEM_BYTES>>>(wv, CH, 0, pht, CH, CHW,
                                              pv, HW, CHW, bv, nullptr, 0, CH, 1.f);
    // S[n][m] = scale * Q . K^T
    mma_gemm<false, false, false><<<gS, 512, SMEM_BYTES>>>(pq, CH, CHW, pk, CH, CHW,
                                               ps, HW, SS, nullptr, nullptr, 0,
                                               CH, 0.04419417382415922f);
    softmax_kernel<<<NB * HW, 256>>>(ps);

    // O^T[n][c]: A = V[c][m], B = attn[n][m], k = m; transposed write
    mma_gemm<true, false, false><<<gP, 512, SMEM_BYTES>>>(pv, HW, CHW, ps, HW, SS,
                                              po, CH, CHW, nullptr, nullptr, 0, HW, 1.f);
    // out[d][n] = Wo . O + bo + x
    mma_gemm<false, true, true><<<gP, 512, SMEM_BYTES>>>(wo, CH, 0, po, CH, CHW,
                                             out, HW, CHW, bo, x, CHW, CH, 1.f);
}

// round 9
// speedup vs baseline: 2.8989x; 2.0851x over previous
#include <cuda_runtime.h>
#include <cuda_fp16.h>
#include <cstdint>

#define NB 4
#define CH 512
#define HW 4096
#define NG 32
#define CPG 16
#define CHW ((long long)CH * HW)   // 2097152
#define SS  ((long long)HW * HW)   // 16777216

// smem geometry (uint32 units): 128 rows x (32 k-u32 + 8 pad) -> stride 40
// BK = 64 halves (128 B/row). Same conflict pattern as validated R5 layout.
#define SM_STRIDE 40
#define SM_OP     (128 * SM_STRIDE)       // 5120 u32 per operand
#define SM_STAGE  (2 * SM_OP)             // A + B per stage
#define SMEM_BYTES (2 * SM_STAGE * 4)     // 81920 B, double buffered

// Scratch (static device globals: allocation-free per harness rules)
static __device__ __half g_wh[4 * CH * CH];                // fp16 weights q,k,v,o
static __device__ __half g_ht[NB * CH * HW];               // H^T  [n][c]
static __device__ __half g_q [NB * CH * HW];               // Q^T  [n][c]
static __device__ __half g_k [NB * CH * HW];               // K^T  [m][c]
static __device__ __half g_v [NB * CH * HW];               // V    [c][m]
static __device__ __half g_o [NB * CH * HW];               // O^T  [n][c]
static __device__ __half g_s [(size_t)NB * HW * HW];       // S    [n][m]

// ---------------------------------------------------------------------------
// helpers
// ---------------------------------------------------------------------------
__device__ __forceinline__ void mma16(float* c, uint32_t a0, uint32_t a1,
                                      uint32_t a2, uint32_t a3,
                                      uint32_t b0, uint32_t b1) {
    asm volatile(
        "mma.sync.aligned.m16n8k16.row.col.f32.f16.f16.f32 "
        "{%0,%1,%2,%3}, {%4,%5,%6,%7}, {%8,%9}, {%0,%1,%2,%3};"
        : "+f"(c[0]), "+f"(c[1]), "+f"(c[2]), "+f"(c[3])
        : "r"(a0), "r"(a1), "r"(a2), "r"(a3), "r"(b0), "r"(b1));
}

__device__ __forceinline__ void cpasync16(uint32_t dst, const void* src) {
    asm volatile("cp.async.cg.shared.global [%0], [%1], 16;" :: "r"(dst), "l"(src));
}

__device__ __forceinline__ uint32_t smem_u32(const void* p) {
    uint32_t a;
    asm("{ .reg .u64 t; cvta.to.shared.u64 t, %1; cvt.u32.u64 %0, t; }" : "=r"(a) : "l"(p));
    return a;
}

// ---------------------------------------------------------------------------
// fp32 -> fp16 weight conversion (CH*CH elems), <<<256,256>>>
// ---------------------------------------------------------------------------
__global__ __launch_bounds__(256) void f2h_kernel(const float* __restrict__ src,
                                                  __half* __restrict__ dst)
{
    int i = blockIdx.x * 256 + threadIdx.x;       // 65536 float4s
    float4 v = ((const float4*)src)[i];
    __half2* d2 = (__half2*)dst;
    d2[2 * i]     = __floats2half2_rn(v.x, v.y);
    d2[2 * i + 1] = __floats2half2_rn(v.z, v.w);
}

// ---------------------------------------------------------------------------
// GroupNorm -> transposed fp16 output H^T[n][c].
// ---------------------------------------------------------------------------
__global__ __launch_bounds__(512) void groupnorm_t_kernel(
    const float* __restrict__ x, const float* __restrict__ gamma,
    const float* __restrict__ beta, __half* __restrict__ ht)
{
    int b = blockIdx.x / NG, grp = blockIdx.x % NG;
    size_t base = ((size_t)b * CH + (size_t)grp * CPG) * HW;
    const float4* x4 = (const float4*)(x + base);
    const int n4 = CPG * HW / 4;  // 16384

    float s = 0.f, ss = 0.f;
    for (int i = threadIdx.x; i < n4; i += blockDim.x) {
        float4 v = x4[i];
        s  += v.x + v.y + v.z + v.w;
        ss += v.x * v.x + v.y * v.y + v.z * v.z + v.w * v.w;
    }
    __shared__ float shs[16], shss[16];
#pragma unroll
    for (int o = 16; o > 0; o >>= 1) {
        s  += __shfl_xor_sync(0xffffffffu, s, o);
        ss += __shfl_xor_sync(0xffffffffu, ss, o);
    }
    int wid = threadIdx.x >> 5, lid = threadIdx.x & 31;
    if (lid == 0) { shs[wid] = s; shss[wid] = ss; }
    __syncthreads();
    if (threadIdx.x == 0) {
        float ts = 0.f, tss = 0.f;
#pragma unroll
        for (int w = 0; w < 16; w++) { ts += shs[w]; tss += shss[w]; }
        shs[0] = ts; shss[0] = tss;
    }
    __syncthreads();
    const float invn = 1.f / (float)(CPG * HW);
    float mean = shs[0] * invn;
    float var  = shss[0] * invn - mean * mean;
    float rstd = rsqrtf(var + 1e-5f);

    int ch  = threadIdx.x >> 5;        // 0..15
    int nl  = threadIdx.x & 31;        // 0..31
    float ga = gamma[grp * CPG + ch] * rstd;
    float be = beta [grp * CPG + ch] - mean * ga;

    __shared__ float sm[16 * 132];
    __half* htp = ht + (size_t)b * CHW;

    for (int tile = 0; tile < HW / 128; tile++) {
        float4 v = x4[ch * (HW / 4) + tile * 32 + nl];
        v.x = v.x * ga + be; v.y = v.y * ga + be;
        v.z = v.z * ga + be; v.w = v.w * ga + be;
        *(float4*)&sm[ch * 132 + nl * 4] = v;
        __syncthreads();
        int i  = threadIdx.x >> 2;     // 0..127
        int c4 = threadIdx.x & 3;      // 0..3
        float4 w;
        w.x = sm[(c4 * 4 + 0) * 132 + i];
        w.y = sm[(c4 * 4 + 1) * 132 + i];
        w.z = sm[(c4 * 4 + 2) * 132 + i];
        w.w = sm[(c4 * 4 + 3) * 132 + i];
        __half2* dst = (__half2*)(htp + (size_t)(tile * 128 + i) * CH + grp * CPG + c4 * 4);
        dst[0] = __floats2half2_rn(w.x, w.y);
        dst[1] = __floats2half2_rn(w.z, w.w);
        __syncthreads();
    }
}

// ---------------------------------------------------------------------------
// Unified fp16 mma GEMM (fp32 accum), cp.async double-buffered, LDS.64 frags.
//   C[m][n] = sum_k A[m][k] * B[n][k]   (both operands k-contiguous fp16)
//   128x128 tile, BK=64 halves, 256 threads (8 warps, 64x32 warp tiles).
//   u32-column permutation (logical c<4 -> phys 2c, c>=4 -> 2(c-4)+1),
//   identical for A & B -> MMA-invariant, enables LDS.64 fragment loads.
// ---------------------------------------------------------------------------
template<bool TRANS, bool HASBIAS, bool OUTF32>
__global__ __launch_bounds__(256, 2) void mma_gemm(
    const __half* __restrict__ A, int ldA, long long aStride,
    const __half* __restrict__ B, int ldB, long long bStride,
    void* __restrict__ Cvoid, int ldC, long long cStride,
    const float* __restrict__ bias,
    const float* __restrict__ resid, long long rStride,
    int K, float scale)
{
    extern __shared__ uint32_t sm[];
    const uint32_t smb = smem_u32(sm);

    const int tid  = threadIdx.x;
    const int lane = tid & 31;
    const int wid  = tid >> 5;
    const int g    = lane >> 2;       // 0..7
    const int t    = lane & 3;        // 0..3
    const int warpM = (wid >> 2) * 64;
    const int warpN = (wid & 3) * 32;

    const int m0 = blockIdx.y * 128, n0 = blockIdx.x * 128;
    const __half* Ap = A + blockIdx.z * aStride;
    const __half* Bp = B + blockIdx.z * bStride;

    // loader: thread covers rows r0 + {0,32,64,96}, fixed 16B (8-half) col kq
    const int r0 = tid >> 3;          // 0..31
    const int kq = tid & 7;

    float acc[4][4][4] = {};

    auto load_stage = [&](int st, int k0) {
        uint32_t dA = smb + (uint32_t)(st * SM_STAGE + r0 * SM_STRIDE + kq * 4) * 4;
        uint32_t dB = dA + SM_OP * 4;
        const __half* sA = Ap + (size_t)(m0 + r0) * ldA + k0 + kq * 8;
        const __half* sB = Bp + (size_t)(n0 + r0) * ldB + k0 + kq * 8;
#pragma unroll
        for (int i = 0; i < 4; i++) {
            cpasync16(dA + (uint32_t)(32 * i * SM_STRIDE) * 4, sA + (size_t)(32 * i) * ldA);
            cpasync16(dB + (uint32_t)(32 * i * SM_STRIDE) * 4, sB + (size_t)(32 * i) * ldB);
        }
    };

    load_stage(0, 0);
    asm volatile("cp.async.commit_group;");

    int s = 0;
    for (int k0 = 0; k0 < K; k0 += 64, s ^= 1) {
        if (k0 + 64 < K) {
            load_stage(s ^ 1, k0 + 64);
            asm volatile("cp.async.commit_group;");
            asm volatile("cp.async.wait_group 1;");
        } else {
            asm volatile("cp.async.wait_group 0;");
        }
        __syncthreads();

        const uint32_t* As = sm + s * SM_STAGE;
        const uint32_t* Bs = As + SM_OP;
#pragma unroll
        for (int kk = 0; kk < 4; kk++) {            // k16 step
            const int kc = kk * 8 + 2 * t;          // phys u32 col pair
            uint32_t af[4][4], bf[4][2];
#pragma unroll
            for (int mt = 0; mt < 4; mt++) {
                int r = warpM + mt * 16 + g;
                uint2 lo = *(const uint2*)&As[(r)     * SM_STRIDE + kc];
                uint2 hi = *(const uint2*)&As[(r + 8) * SM_STRIDE + kc];
                af[mt][0] = lo.x; af[mt][1] = hi.x;
                af[mt][2] = lo.y; af[mt][3] = hi.y;
            }
#pragma unroll
            for (int nt = 0; nt < 4; nt++) {
                int r = warpN + nt * 8 + g;
                uint2 bb = *(const uint2*)&Bs[r * SM_STRIDE + kc];
                bf[nt][0] = bb.x; bf[nt][1] = bb.y;
            }
#pragma unroll
            for (int mt = 0; mt < 4; mt++)
#pragma unroll
                for (int nt = 0; nt < 4; nt++)
                    mma16(acc[mt][nt], af[mt][0], af[mt][1], af[mt][2], af[mt][3],
                          bf[nt][0], bf[nt][1]);
        }
        __syncthreads();
    }

    // epilogue
#pragma unroll
    for (int mt = 0; mt < 4; mt++) {
        int row = m0 + warpM + mt * 16 + g;
        float b0 = 0.f, b1 = 0.f;
        if (HASBIAS) { b0 = bias[row]; b1 = bias[row + 8]; }
#pragma unroll
        for (int nt = 0; nt < 4; nt++) {
            int col = n0 + warpN + nt * 8 + 2 * t;
            float v0 = acc[mt][nt][0] * scale + b0;
            float v1 = acc[mt][nt][1] * scale + b0;
            float v2 = acc[mt][nt][2] * scale + b1;
            float v3 = acc[mt][nt][3] * scale + b1;
            if (OUTF32) {
                float* Cf = (float*)Cvoid + blockIdx.z * cStride;
                const float* Rp = resid + blockIdx.z * rStride;
                float2 r0v = *(const float2*)(Rp + (size_t)row * ldC + col);
                float2 r1v = *(const float2*)(Rp + (size_t)(row + 8) * ldC + col);
                v0 += r0v.x; v1 += r0v.y; v2 += r1v.x; v3 += r1v.y;
                *(float2*)(Cf + (size_t)row * ldC + col)       = make_float2(v0, v1);
                *(float2*)(Cf + (size_t)(row + 8) * ldC + col) = make_float2(v2, v3);
            } else {
                __half* Ch = (__half*)Cvoid + blockIdx.z * cStride;
                if (TRANS) {
                    Ch[(size_t)(col)     * ldC + row    ] = __float2half_rn(v0);
                    Ch[(size_t)(col + 1) * ldC + row    ] = __float2half_rn(v1);
                    Ch[(size_t)(col)     * ldC + row + 8] = __float2half_rn(v2);
                    Ch[(size_t)(col + 1) * ldC + row + 8] = __float2half_rn(v3);
                } else {
                    *(__half2*)(Ch + (size_t)row * ldC + col)       = __floats2half2_rn(v0, v1);
                    *(__half2*)(Ch + (size_t)(row + 8) * ldC + col) = __floats2half2_rn(v2, v3);
                }
            }
        }
    }
}

// ---------------------------------------------------------------------------
// Row softmax in place over last dim (4096), fp16 storage, fp32 math.
// ---------------------------------------------------------------------------
__global__ __launch_bounds__(256) void softmax_h_kernel(__half* __restrict__ S)
{
    __half2* p2 = (__half2*)(S + (size_t)blockIdx.x * HW);   // 2048 half2
    int tid = threadIdx.x;
    float2 v[8];
    float mx = -3.0e38f;
#pragma unroll
    for (int i = 0; i < 8; i++) {
        v[i] = __half22float2(p2[tid + i * 256]);
        mx = fmaxf(mx, fmaxf(v[i].x, v[i].y));
    }
    __shared__ float red[8];
#pragma unroll
    for (int o = 16; o > 0; o >>= 1) mx = fmaxf(mx, __shfl_xor_sync(0xffffffffu, mx, o));
    if ((tid & 31) == 0) red[tid >> 5] = mx;
    __syncthreads();
    mx = red[0];
#pragma unroll
    for (int w = 1; w < 8; w++) mx = fmaxf(mx, red[w]);

    float sum = 0.f;
#pragma unroll
    for (int i = 0; i < 8; i++) {
        v[i].x = __expf(v[i].x - mx); v[i].y = __expf(v[i].y - mx);
        sum += v[i].x + v[i].y;
    }
#pragma unroll
    for (int o = 16; o > 0; o >>= 1) sum += __shfl_xor_sync(0xffffffffu, sum, o);
    __syncthreads();
    if ((tid & 31) == 0) red[tid >> 5] = sum;
    __syncthreads();
    sum = 0.f;
#pragma unroll
    for (int w = 0; w < 8; w++) sum += red[w];
    float inv = 1.f / sum;
#pragma unroll
    for (int i = 0; i < 8; i++)
        p2[tid + i * 256] = __floats2half2_rn(v[i].x * inv, v[i].y * inv);
}

// ---------------------------------------------------------------------------
extern "C" void kernel_launch(void* const* d_in, const int* in_sizes, int n_in,
                              void* d_out, int out_size)
{
    const float* x     = (const float*)d_in[0];
    const float* gamma = (const float*)d_in[1];
    const float* beta  = (const float*)d_in[2];
    const float* wq    = (const float*)d_in[3];
    const float* bq    = (const float*)d_in[4];
    const float* wk    = (const float*)d_in[5];
    const float* bk    = (const float*)d_in[6];
    const float* wv    = (const float*)d_in[7];
    const float* bv    = (const float*)d_in[8];
    const float* wo    = (const float*)d_in[9];
    const float* bo    = (const float*)d_in[10];
    float* out = (float*)d_out;

    __half *pwh, *pht, *pq, *pk, *pv, *po, *ps;
    cudaGetSymbolAddress((void**)&pwh, g_wh);
    cudaGetSymbolAddress((void**)&pht, g_ht);
    cudaGetSymbolAddress((void**)&pq,  g_q);
    cudaGetSymbolAddress((void**)&pk,  g_k);
    cudaGetSymbolAddress((void**)&pv,  g_v);
    cudaGetSymbolAddress((void**)&po,  g_o);
    cudaGetSymbolAddress((void**)&ps,  g_s);

    cudaFuncSetAttribute(mma_gemm<true,  true,  false>, cudaFuncAttributeMaxDynamicSharedMemorySize, SMEM_BYTES);
    cudaFuncSetAttribute(mma_gemm<false, true,  false>, cudaFuncAttributeMaxDynamicSharedMemorySize, SMEM_BYTES);
    cudaFuncSetAttribute(mma_gemm<false, false, false>, cudaFuncAttributeMaxDynamicSharedMemorySize, SMEM_BYTES);
    cudaFuncSetAttribute(mma_gemm<true,  false, false>, cudaFuncAttributeMaxDynamicSharedMemorySize, SMEM_BYTES);
    cudaFuncSetAttribute(mma_gemm<false, true,  true >, cudaFuncAttributeMaxDynamicSharedMemorySize, SMEM_BYTES);

    // weights -> fp16
    f2h_kernel<<<256, 256>>>(wq, pwh + 0 * CH * CH);
    f2h_kernel<<<256, 256>>>(wk, pwh + 1 * CH * CH);
    f2h_kernel<<<256, 256>>>(wv, pwh + 2 * CH * CH);
    f2h_kernel<<<256, 256>>>(wo, pwh + 3 * CH * CH);

    // GroupNorm -> H^T[n][c] fp16
    groupnorm_t_kernel<<<NB * NG, 512>>>(x, gamma, beta, pht);

    dim3 gP(HW / 128, CH / 128, NB);   // proj GEMMs: M=512, N=4096
    dim3 gS(HW / 128, HW / 128, NB);   // scores: M=N=4096

    // Q^T = (Wq . H)^T, transposed epilogue
    mma_gemm<true, true, false><<<gP, 256, SMEM_BYTES>>>(pwh + 0 * CH * CH, CH, 0,
        pht, CH, CHW, pq, CH, CHW, bq, nullptr, 0, CH, 1.f);
    // K^T
    mma_gemm<true, true, false><<<gP, 256, SMEM_BYTES>>>(pwh + 1 * CH * CH, CH, 0,
        pht, CH, CHW, pk, CH, CHW, bk, nullptr, 0, CH, 1.f);
    // V natural [d][n]
    mma_gemm<false, true, false><<<gP, 256, SMEM_BYTES>>>(pwh + 2 * CH * CH, CH, 0,
        pht, CH, CHW, pv, HW, CHW, bv, nullptr, 0, CH, 1.f);
    // S[n][m] = scale * Q . K^T
    mma_gemm<false, false, false><<<gS, 256, SMEM_BYTES>>>(pq, CH, CHW, pk, CH, CHW,
        ps, HW, SS, nullptr, nullptr, 0, CH, 0.04419417382415922f);
    softmax_h_kernel<<<NB * HW, 256>>>(ps);

    // O^T[n][c]: A = V[c][m], B = attn[n][m], k = m; transposed write
    mma_gemm<true, false, false><<<gP, 256, SMEM_BYTES>>>(pv, HW, CHW, ps, HW, SS,
        po, CH, CHW, nullptr, nullptr, 0, HW, 1.f);
    // out[d][n] = Wo . O + bo + x  (fp32 out + residual)
    mma_gemm<false, true, true><<<gP, 256, SMEM_BYTES>>>(pwh + 3 * CH * CH, CH, 0,
        po, CH, CHW, out, HW, CHW, bo, x, CHW, CH, 1.f);
}

// round 10
// speedup vs baseline: 2.9721x; 1.0253x over previous
#include <cuda_runtime.h>
#include <cuda_fp16.h>
#include <cstdint>

#define NB 4
#define CH 512
#define HW 4096
#define NG 32
#define CPG 16
#define CHW ((long long)CH * HW)   // 2097152
#define SS  ((long long)HW * HW)   // 16777216

// smem geometry (uint32 units): 128 rows x (32 k-u32 + 4 pad) -> stride 36
// stride 36 (=4 mod 32): each LDSM 8-row phase hits 8 disjoint bank quads.
#define SM_STRIDE 36
#define SM_OP     (128 * SM_STRIDE)       // 4608 u32 per operand
#define SM_STAGE  (2 * SM_OP)             // A + B per stage
#define SMEM_BYTES (2 * SM_STAGE * 4)     // 73728 B, double buffered

// Scratch (static device globals: allocation-free per harness rules)
static __device__ __half g_wh[4 * CH * CH];                // fp16 weights q,k,v,o
static __device__ __half g_ht[NB * CH * HW];               // H^T  [n][c]
static __device__ __half g_q [NB * CH * HW];               // Q^T  [n][c]
static __device__ __half g_k [NB * CH * HW];               // K^T  [m][c]
static __device__ __half g_v [NB * CH * HW];               // V    [c][m]
static __device__ __half g_o [NB * CH * HW];               // O^T  [n][c]
static __device__ __half g_s [(size_t)NB * HW * HW];       // S    [n][m]

// ---------------------------------------------------------------------------
// helpers
// ---------------------------------------------------------------------------
__device__ __forceinline__ void mma16(float* c, uint32_t a0, uint32_t a1,
                                      uint32_t a2, uint32_t a3,
                                      uint32_t b0, uint32_t b1) {
    asm volatile(
        "mma.sync.aligned.m16n8k16.row.col.f32.f16.f16.f32 "
        "{%0,%1,%2,%3}, {%4,%5,%6,%7}, {%8,%9}, {%0,%1,%2,%3};"
        : "+f"(c[0]), "+f"(c[1]), "+f"(c[2]), "+f"(c[3])
        : "r"(a0), "r"(a1), "r"(a2), "r"(a3), "r"(b0), "r"(b1));
}

__device__ __forceinline__ void ldsm4(uint32_t& r0, uint32_t& r1,
                                      uint32_t& r2, uint32_t& r3, uint32_t a) {
    asm volatile("ldmatrix.sync.aligned.m8n8.x4.shared.b16 {%0,%1,%2,%3}, [%4];"
                 : "=r"(r0), "=r"(r1), "=r"(r2), "=r"(r3) : "r"(a));
}

__device__ __forceinline__ void cpasync16(uint32_t dst, const void* src) {
    asm volatile("cp.async.cg.shared.global [%0], [%1], 16;" :: "r"(dst), "l"(src));
}

__device__ __forceinline__ uint32_t smem_u32(const void* p) {
    uint32_t a;
    asm("{ .reg .u64 t; cvta.to.shared.u64 t, %1; cvt.u32.u64 %0, t; }" : "=r"(a) : "l"(p));
    return a;
}

// ---------------------------------------------------------------------------
// fp32 -> fp16 conversion of all 4 weight matrices in one launch. grid 1024.
// ---------------------------------------------------------------------------
__global__ __launch_bounds__(256) void f2h4_kernel(
    const float* __restrict__ w0, const float* __restrict__ w1,
    const float* __restrict__ w2, const float* __restrict__ w3,
    __half* __restrict__ dst)
{
    int which = blockIdx.x >> 8;                  // 0..3
    int i = (blockIdx.x & 255) * 256 + threadIdx.x;  // 65536 float4s per weight
    const float* src = which == 0 ? w0 : which == 1 ? w1 : which == 2 ? w2 : w3;
    float4 v = ((const float4*)src)[i];
    __half2* d2 = (__half2*)(dst + (size_t)which * CH * CH);
    d2[2 * i]     = __floats2half2_rn(v.x, v.y);
    d2[2 * i + 1] = __floats2half2_rn(v.z, v.w);
}

// ---------------------------------------------------------------------------
// GroupNorm -> transposed fp16 output H^T[n][c].
// ---------------------------------------------------------------------------
__global__ __launch_bounds__(512) void groupnorm_t_kernel(
    const float* __restrict__ x, const float* __restrict__ gamma,
    const float* __restrict__ beta, __half* __restrict__ ht)
{
    int b = blockIdx.x / NG, grp = blockIdx.x % NG;
    size_t base = ((size_t)b * CH + (size_t)grp * CPG) * HW;
    const float4* x4 = (const float4*)(x + base);
    const int n4 = CPG * HW / 4;  // 16384

    float s = 0.f, ss = 0.f;
    for (int i = threadIdx.x; i < n4; i += blockDim.x) {
        float4 v = x4[i];
        s  += v.x + v.y + v.z + v.w;
        ss += v.x * v.x + v.y * v.y + v.z * v.z + v.w * v.w;
    }
    __shared__ float shs[16], shss[16];
#pragma unroll
    for (int o = 16; o > 0; o >>= 1) {
        s  += __shfl_xor_sync(0xffffffffu, s, o);
        ss += __shfl_xor_sync(0xffffffffu, ss, o);
    }
    int wid = threadIdx.x >> 5, lid = threadIdx.x & 31;
    if (lid == 0) { shs[wid] = s; shss[wid] = ss; }
    __syncthreads();
    if (threadIdx.x == 0) {
        float ts = 0.f, tss = 0.f;
#pragma unroll
        for (int w = 0; w < 16; w++) { ts += shs[w]; tss += shss[w]; }
        shs[0] = ts; shss[0] = tss;
    }
    __syncthreads();
    const float invn = 1.f / (float)(CPG * HW);
    float mean = shs[0] * invn;
    float var  = shss[0] * invn - mean * mean;
    float rstd = rsqrtf(var + 1e-5f);

    int ch  = threadIdx.x >> 5;        // 0..15
    int nl  = threadIdx.x & 31;        // 0..31
    float ga = gamma[grp * CPG + ch] * rstd;
    float be = beta [grp * CPG + ch] - mean * ga;

    __shared__ float sm[16 * 132];
    __half* htp = ht + (size_t)b * CHW;

    for (int tile = 0; tile < HW / 128; tile++) {
        float4 v = x4[ch * (HW / 4) + tile * 32 + nl];
        v.x = v.x * ga + be; v.y = v.y * ga + be;
        v.z = v.z * ga + be; v.w = v.w * ga + be;
        *(float4*)&sm[ch * 132 + nl * 4] = v;
        __syncthreads();
        int i  = threadIdx.x >> 2;     // 0..127
        int c4 = threadIdx.x & 3;      // 0..3
        float4 w;
        w.x = sm[(c4 * 4 + 0) * 132 + i];
        w.y = sm[(c4 * 4 + 1) * 132 + i];
        w.z = sm[(c4 * 4 + 2) * 132 + i];
        w.w = sm[(c4 * 4 + 3) * 132 + i];
        __half2* dst = (__half2*)(htp + (size_t)(tile * 128 + i) * CH + grp * CPG + c4 * 4);
        dst[0] = __floats2half2_rn(w.x, w.y);
        dst[1] = __floats2half2_rn(w.z, w.w);
        __syncthreads();
    }
}

// ---------------------------------------------------------------------------
// Unified fp16 mma GEMM (fp32 accum), cp.async double-buffered, LDSM frags.
//   C[m][n] = sum_k A[m][k] * B[n][k]   (both operands k-contiguous fp16)
//   128x128 tile, BK=64 halves, 256 threads (8 warps, 64x32 warp tiles).
//   Canonical fragment layout via ldmatrix.m8n8.x4 (A: 4/kk, B: 2/kk).
// ---------------------------------------------------------------------------
template<bool TRANS, bool HASBIAS, bool OUTF32>
__global__ __launch_bounds__(256, 2) void mma_gemm(
    const __half* __restrict__ A, int ldA, long long aStride,
    const __half* __restrict__ B, int ldB, long long bStride,
    void* __restrict__ Cvoid, int ldC, long long cStride,
    const float* __restrict__ bias,
    const float* __restrict__ resid, long long rStride,
    int K, float scale)
{
    extern __shared__ uint32_t sm[];
    const uint32_t smb = smem_u32(sm);

    const int tid  = threadIdx.x;
    const int lane = tid & 31;
    const int wid  = tid >> 5;
    const int g    = lane >> 2;       // 0..7
    const int t    = lane & 3;        // 0..3
    const int warpM = (wid >> 2) * 64;
    const int warpN = (wid & 3) * 32;

    const int m0 = blockIdx.y * 128, n0 = blockIdx.x * 128;
    const __half* Ap = A + blockIdx.z * aStride;
    const __half* Bp = B + blockIdx.z * bStride;

    // loader: thread covers rows r0 + {0,32,64,96}, fixed 16B (8-half) col kq
    const int r0 = tid >> 3;          // 0..31
    const int kq = tid & 7;

    // LDSM lane offsets (u32 units within operand)
    // A x4 tiles: (m0-7,klo),(m8-15,klo),(m0-7,khi),(m8-15,khi) -> a0..a3
    const int l15 = lane & 15, lhi = lane >> 4;
    int offA[4];
#pragma unroll
    for (int mt = 0; mt < 4; mt++)
        offA[mt] = (warpM + mt * 16 + l15) * SM_STRIDE + lhi * 4;
    // B x4 tiles: (nt0,klo),(nt0,khi),(nt1,klo),(nt1,khi) -> b0,b1 of 2 n-tiles
    const int sub = lane >> 3, l7 = lane & 7;
    int offB[2];
#pragma unroll
    for (int p = 0; p < 2; p++)
        offB[p] = (warpN + (2 * p + (sub >> 1)) * 8 + l7) * SM_STRIDE + (sub & 1) * 4;

    float acc[4][4][4] = {};

    auto load_stage = [&](int st, int k0) {
        uint32_t dA = smb + (uint32_t)(st * SM_STAGE + r0 * SM_STRIDE + kq * 4) * 4;
        uint32_t dB = dA + SM_OP * 4;
        const __half* sA = Ap + (size_t)(m0 + r0) * ldA + k0 + kq * 8;
        const __half* sB = Bp + (size_t)(n0 + r0) * ldB + k0 + kq * 8;
#pragma unroll
        for (int i = 0; i < 4; i++) {
            cpasync16(dA + (uint32_t)(32 * i * SM_STRIDE) * 4, sA + (size_t)(32 * i) * ldA);
            cpasync16(dB + (uint32_t)(32 * i * SM_STRIDE) * 4, sB + (size_t)(32 * i) * ldB);
        }
    };

    load_stage(0, 0);
    asm volatile("cp.async.commit_group;");

    int s = 0;
    for (int k0 = 0; k0 < K; k0 += 64, s ^= 1) {
        if (k0 + 64 < K) {
            load_stage(s ^ 1, k0 + 64);
            asm volatile("cp.async.commit_group;");
            asm volatile("cp.async.wait_group 1;");
        } else {
            asm volatile("cp.async.wait_group 0;");
        }
        __syncthreads();

        const uint32_t stA = smb + (uint32_t)(s * SM_STAGE) * 4;
        const uint32_t stB = stA + SM_OP * 4;
#pragma unroll
        for (int kk = 0; kk < 4; kk++) {            // k16 step = 8 u32 cols
            uint32_t af[4][4], bf[2][4];
#pragma unroll
            for (int mt = 0; mt < 4; mt++)
                ldsm4(af[mt][0], af[mt][1], af[mt][2], af[mt][3],
                      stA + (uint32_t)(offA[mt] + kk * 8) * 4);
#pragma unroll
            for (int p = 0; p < 2; p++)
                ldsm4(bf[p][0], bf[p][1], bf[p][2], bf[p][3],
                      stB + (uint32_t)(offB[p] + kk * 8) * 4);
#pragma unroll
            for (int mt = 0; mt < 4; mt++)
#pragma unroll
                for (int nt = 0; nt < 4; nt++)
                    mma16(acc[mt][nt], af[mt][0], af[mt][1], af[mt][2], af[mt][3],
                          bf[nt >> 1][(nt & 1) * 2], bf[nt >> 1][(nt & 1) * 2 + 1]);
        }
        __syncthreads();
    }

    // epilogue
#pragma unroll
    for (int mt = 0; mt < 4; mt++) {
        int row = m0 + warpM + mt * 16 + g;
        float b0 = 0.f, b1 = 0.f;
        if (HASBIAS) { b0 = bias[row]; b1 = bias[row + 8]; }
#pragma unroll
        for (int nt = 0; nt < 4; nt++) {
            int col = n0 + warpN + nt * 8 + 2 * t;
            float v0 = acc[mt][nt][0] * scale + b0;
            float v1 = acc[mt][nt][1] * scale + b0;
            float v2 = acc[mt][nt][2] * scale + b1;
            float v3 = acc[mt][nt][3] * scale + b1;
            if (OUTF32) {
                float* Cf = (float*)Cvoid + blockIdx.z * cStride;
                const float* Rp = resid + blockIdx.z * rStride;
                float2 r0v = *(const float2*)(Rp + (size_t)row * ldC + col);
                float2 r1v = *(const float2*)(Rp + (size_t)(row + 8) * ldC + col);
                v0 += r0v.x; v1 += r0v.y; v2 += r1v.x; v3 += r1v.y;
                *(float2*)(Cf + (size_t)row * ldC + col)       = make_float2(v0, v1);
                *(float2*)(Cf + (size_t)(row + 8) * ldC + col) = make_float2(v2, v3);
            } else {
                __half* Ch = (__half*)Cvoid + blockIdx.z * cStride;
                if (TRANS) {
                    Ch[(size_t)(col)     * ldC + row    ] = __float2half_rn(v0);
                    Ch[(size_t)(col + 1) * ldC + row    ] = __float2half_rn(v1);
                    Ch[(size_t)(col)     * ldC + row + 8] = __float2half_rn(v2);
                    Ch[(size_t)(col + 1) * ldC + row + 8] = __float2half_rn(v3);
                } else {
                    *(__half2*)(Ch + (size_t)row * ldC + col)       = __floats2half2_rn(v0, v1);
                    *(__half2*)(Ch + (size_t)(row + 8) * ldC + col) = __floats2half2_rn(v2, v3);
                }
            }
        }
    }
}

// ---------------------------------------------------------------------------
// Row softmax in place over last dim (4096), fp16 storage, fp32 math.
// ---------------------------------------------------------------------------
__global__ __launch_bounds__(256) void softmax_h_kernel(__half* __restrict__ S)
{
    __half2* p2 = (__half2*)(S + (size_t)blockIdx.x * HW);   // 2048 half2
    int tid = threadIdx.x;
    float2 v[8];
    float mx = -3.0e38f;
#pragma unroll
    for (int i = 0; i < 8; i++) {
        v[i] = __half22float2(p2[tid + i * 256]);
        mx = fmaxf(mx, fmaxf(v[i].x, v[i].y));
    }
    __shared__ float red[8];
#pragma unroll
    for (int o = 16; o > 0; o >>= 1) mx = fmaxf(mx, __shfl_xor_sync(0xffffffffu, mx, o));
    if ((tid & 31) == 0) red[tid >> 5] = mx;
    __syncthreads();
    mx = red[0];
#pragma unroll
    for (int w = 1; w < 8; w++) mx = fmaxf(mx, red[w]);

    float sum = 0.f;
#pragma unroll
    for (int i = 0; i < 8; i++) {
        v[i].x = __expf(v[i].x - mx); v[i].y = __expf(v[i].y - mx);
        sum += v[i].x + v[i].y;
    }
#pragma unroll
    for (int o = 16; o > 0; o >>= 1) sum += __shfl_xor_sync(0xffffffffu, sum, o);
    __syncthreads();
    if ((tid & 31) == 0) red[tid >> 5] = sum;
    __syncthreads();
    sum = 0.f;
#pragma unroll
    for (int w = 0; w < 8; w++) sum += red[w];
    float inv = 1.f / sum;
#pragma unroll
    for (int i = 0; i < 8; i++)
        p2[tid + i * 256] = __floats2half2_rn(v[i].x * inv, v[i].y * inv);
}

// ---------------------------------------------------------------------------
extern "C" void kernel_launch(void* const* d_in, const int* in_sizes, int n_in,
                              void* d_out, int out_size)
{
    const float* x     = (const float*)d_in[0];
    const float* gamma = (const float*)d_in[1];
    const float* beta  = (const float*)d_in[2];
    const float* wq    = (const float*)d_in[3];
    const float* bq    = (const float*)d_in[4];
    const float* wk    = (const float*)d_in[5];
    const float* bk    = (const float*)d_in[6];
    const float* wv    = (const float*)d_in[7];
    const float* bv    = (const float*)d_in[8];
    const float* wo    = (const float*)d_in[9];
    const float* bo    = (const float*)d_in[10];
    float* out = (float*)d_out;

    __half *pwh, *pht, *pq, *pk, *pv, *po, *ps;
    cudaGetSymbolAddress((void**)&pwh, g_wh);
    cudaGetSymbolAddress((void**)&pht, g_ht);
    cudaGetSymbolAddress((void**)&pq,  g_q);
    cudaGetSymbolAddress((void**)&pk,  g_k);
    cudaGetSymbolAddress((void**)&pv,  g_v);
    cudaGetSymbolAddress((void**)&po,  g_o);
    cudaGetSymbolAddress((void**)&ps,  g_s);

    cudaFuncSetAttribute(mma_gemm<true,  true,  false>, cudaFuncAttributeMaxDynamicSharedMemorySize, SMEM_BYTES);
    cudaFuncSetAttribute(mma_gemm<false, true,  false>, cudaFuncAttributeMaxDynamicSharedMemorySize, SMEM_BYTES);
    cudaFuncSetAttribute(mma_gemm<false, false, false>, cudaFuncAttributeMaxDynamicSharedMemorySize, SMEM_BYTES);
    cudaFuncSetAttribute(mma_gemm<true,  false, false>, cudaFuncAttributeMaxDynamicSharedMemorySize, SMEM_BYTES);
    cudaFuncSetAttribute(mma_gemm<false, true,  true >, cudaFuncAttributeMaxDynamicSharedMemorySize, SMEM_BYTES);

    // weights -> fp16 (one launch)
    f2h4_kernel<<<1024, 256>>>(wq, wk, wv, wo, pwh);

    // GroupNorm -> H^T[n][c] fp16
    groupnorm_t_kernel<<<NB * NG, 512>>>(x, gamma, beta, pht);

    dim3 gP(HW / 128, CH / 128, NB);   // proj GEMMs: M=512, N=4096
    dim3 gS(HW / 128, HW / 128, NB);   // scores: M=N=4096

    // Q^T = (Wq . H)^T, transposed epilogue
    mma_gemm<true, true, false><<<gP, 256, SMEM_BYTES>>>(pwh + 0 * CH * CH, CH, 0,
        pht, CH, CHW, pq, CH, CHW, bq, nullptr, 0, CH, 1.f);
    // K^T
    mma_gemm<true, true, false><<<gP, 256, SMEM_BYTES>>>(pwh + 1 * CH * CH, CH, 0,
        pht, CH, CHW, pk, CH, CHW, bk, nullptr, 0, CH, 1.f);
    // V natural [d][n]
    mma_gemm<false, true, false><<<gP, 256, SMEM_BYTES>>>(pwh + 2 * CH * CH, CH, 0,
        pht, CH, CHW, pv, HW, CHW, bv, nullptr, 0, CH, 1.f);
    // S[n][m] = scale * Q . K^T
    mma_gemm<false, false, false><<<gS, 256, SMEM_BYTES>>>(pq, CH, CHW, pk, CH, CHW,
        ps, HW, SS, nullptr, nullptr, 0, CH, 0.04419417382415922f);
    softmax_h_kernel<<<NB * HW, 256>>>(ps);

    // O^T[n][c]: A = V[c][m], B = attn[n][m], k = m; transposed write
    mma_gemm<true, false, false><<<gP, 256, SMEM_BYTES>>>(pv, HW, CHW, ps, HW, SS,
        po, CH, CHW, nullptr, nullptr, 0, HW, 1.f);
    // out[d][n] = Wo . O + bo + x  (fp32 out + residual)
    mma_gemm<false, true, true><<<gP, 256, SMEM_BYTES>>>(pwh + 3 * CH * CH, CH, 0,
        po, CH, CHW, out, HW, CHW, bo, x, CHW, CH, 1.f);
}

// round 16
// speedup vs baseline: 2.9761x; 1.0013x over previous
#include <cuda_runtime.h>
#include <cuda_fp16.h>
#include <cstdint>

#define NB 4
#define CH 512
#define HW 4096
#define NG 32
#define CPG 16
#define CHW ((long long)CH * HW)   // 2097152
#define SS  ((long long)HW * HW)   // 16777216

// smem geometry (uint32 units): 128 rows x (32 k-u32 + 4 pad) -> stride 36
// stride 36 (=4 mod 32): each LDSM 8-row phase hits 8 disjoint bank quads.
#define SM_STRIDE 36
#define SM_OP     (128 * SM_STRIDE)       // 4608 u32 per operand
#define SM_STAGE  (2 * SM_OP)             // A + B per stage
#define NSTAGE    3
#define SMEM_BYTES (NSTAGE * SM_STAGE * 4)   // 110592 B, triple buffered

// Scratch (static device globals: allocation-free per harness rules)
static __device__ __half g_wh[4 * CH * CH];                // fp16 weights q,k,v,o
static __device__ __half g_ht[NB * CH * HW];               // H^T  [n][c]
static __device__ __half g_q [NB * CH * HW];               // Q^T  [n][c]
static __device__ __half g_k [NB * CH * HW];               // K^T  [m][c]
static __device__ __half g_v [NB * CH * HW];               // V    [c][m]
static __device__ __half g_o [NB * CH * HW];               // O^T  [n][c]
static __device__ __half g_s [(size_t)NB * HW * HW];       // S    [n][m]

// ---------------------------------------------------------------------------
// helpers
// ---------------------------------------------------------------------------
__device__ __forceinline__ void mma16(float* c, uint32_t a0, uint32_t a1,
                                      uint32_t a2, uint32_t a3,
                                      uint32_t b0, uint32_t b1) {
    asm volatile(
        "mma.sync.aligned.m16n8k16.row.col.f32.f16.f16.f32 "
        "{%0,%1,%2,%3}, {%4,%5,%6,%7}, {%8,%9}, {%0,%1,%2,%3};"
        : "+f"(c[0]), "+f"(c[1]), "+f"(c[2]), "+f"(c[3])
        : "r"(a0), "r"(a1), "r"(a2), "r"(a3), "r"(b0), "r"(b1));
}

__device__ __forceinline__ void ldsm4(uint32_t& r0, uint32_t& r1,
                                      uint32_t& r2, uint32_t& r3, uint32_t a) {
    asm volatile("ldmatrix.sync.aligned.m8n8.x4.shared.b16 {%0,%1,%2,%3}, [%4];"
                 : "=r"(r0), "=r"(r1), "=r"(r2), "=r"(r3) : "r"(a));
}

__device__ __forceinline__ void cpasync16(uint32_t dst, const void* src) {
    asm volatile("cp.async.cg.shared.global [%0], [%1], 16;" :: "r"(dst), "l"(src));
}

__device__ __forceinline__ uint32_t smem_u32(const void* p) {
    uint32_t a;
    asm("{ .reg .u64 t; cvta.to.shared.u64 t, %1; cvt.u32.u64 %0, t; }" : "=r"(a) : "l"(p));
    return a;
}

// ---------------------------------------------------------------------------
// fp32 -> fp16 conversion of all 4 weight matrices in one launch. grid 1024.
// ---------------------------------------------------------------------------
__global__ __launch_bounds__(256) void f2h4_kernel(
    const float* __restrict__ w0, const float* __restrict__ w1,
    const float* __restrict__ w2, const float* __restrict__ w3,
    __half* __restrict__ dst)
{
    int which = blockIdx.x >> 8;                  // 0..3
    int i = (blockIdx.x & 255) * 256 + threadIdx.x;  // 65536 float4s per weight
    const float* src = which == 0 ? w0 : which == 1 ? w1 : which == 2 ? w2 : w3;
    float4 v = ((const float4*)src)[i];
    __half2* d2 = (__half2*)(dst + (size_t)which * CH * CH);
    d2[2 * i]     = __floats2half2_rn(v.x, v.y);
    d2[2 * i + 1] = __floats2half2_rn(v.z, v.w);
}

// ---------------------------------------------------------------------------
// GroupNorm -> transposed fp16 output H^T[n][c].
// ---------------------------------------------------------------------------
__global__ __launch_bounds__(512) void groupnorm_t_kernel(
    const float* __restrict__ x, const float* __restrict__ gamma,
    const float* __restrict__ beta, __half* __restrict__ ht)
{
    int b = blockIdx.x / NG, grp = blockIdx.x % NG;
    size_t base = ((size_t)b * CH + (size_t)grp * CPG) * HW;
    const float4* x4 = (const float4*)(x + base);
    const int n4 = CPG * HW / 4;  // 16384

    float s = 0.f, ss = 0.f;
    for (int i = threadIdx.x; i < n4; i += blockDim.x) {
        float4 v = x4[i];
        s  += v.x + v.y + v.z + v.w;
        ss += v.x * v.x + v.y * v.y + v.z * v.z + v.w * v.w;
    }
    __shared__ float shs[16], shss[16];
#pragma unroll
    for (int o = 16; o > 0; o >>= 1) {
        s  += __shfl_xor_sync(0xffffffffu, s, o);
        ss += __shfl_xor_sync(0xffffffffu, ss, o);
    }
    int wid = threadIdx.x >> 5, lid = threadIdx.x & 31;
    if (lid == 0) { shs[wid] = s; shss[wid] = ss; }
    __syncthreads();
    if (threadIdx.x == 0) {
        float ts = 0.f, tss = 0.f;
#pragma unroll
        for (int w = 0; w < 16; w++) { ts += shs[w]; tss += shss[w]; }
        shs[0] = ts; shss[0] = tss;
    }
    __syncthreads();
    const float invn = 1.f / (float)(CPG * HW);
    float mean = shs[0] * invn;
    float var  = shss[0] * invn - mean * mean;
    float rstd = rsqrtf(var + 1e-5f);

    int ch  = threadIdx.x >> 5;        // 0..15
    int nl  = threadIdx.x & 31;        // 0..31
    float ga = gamma[grp * CPG + ch] * rstd;
    float be = beta [grp * CPG + ch] - mean * ga;

    __shared__ float sm[16 * 132];
    __half* htp = ht + (size_t)b * CHW;

    for (int tile = 0; tile < HW / 128; tile++) {
        float4 v = x4[ch * (HW / 4) + tile * 32 + nl];
        v.x = v.x * ga + be; v.y = v.y * ga + be;
        v.z = v.z * ga + be; v.w = v.w * ga + be;
        *(float4*)&sm[ch * 132 + nl * 4] = v;
        __syncthreads();
        int i  = threadIdx.x >> 2;     // 0..127
        int c4 = threadIdx.x & 3;      // 0..3
        float4 w;
        w.x = sm[(c4 * 4 + 0) * 132 + i];
        w.y = sm[(c4 * 4 + 1) * 132 + i];
        w.z = sm[(c4 * 4 + 2) * 132 + i];
        w.w = sm[(c4 * 4 + 3) * 132 + i];
        __half2* dst = (__half2*)(htp + (size_t)(tile * 128 + i) * CH + grp * CPG + c4 * 4);
        dst[0] = __floats2half2_rn(w.x, w.y);
        dst[1] = __floats2half2_rn(w.z, w.w);
        __syncthreads();
    }
}

// ---------------------------------------------------------------------------
// Unified fp16 mma GEMM (fp32 accum), 3-stage cp.async ring, LDSM frags,
// ONE __syncthreads per k-tile.
//   C[m][n] = sum_k A[m][k] * B[n][k]   (both operands k-contiguous fp16)
//   128x128 tile, BK=64 halves, 256 threads (8 warps, 64x32 warp tiles).
//   iter c: wait(chunk c) -> sync -> prefetch chunk c+2 into stage (c+2)%3
//   (safe: that stage held chunk c-1, finished by this sync) -> compute c.
// ---------------------------------------------------------------------------
template<bool TRANS, bool HASBIAS, bool OUTF32>
__global__ __launch_bounds__(256, 2) void mma_gemm(
    const __half* __restrict__ A, int ldA, long long aStride,
    const __half* __restrict__ B, int ldB, long long bStride,
    void* __restrict__ Cvoid, int ldC, long long cStride,
    const float* __restrict__ bias,
    const float* __restrict__ resid, long long rStride,
    int K, float scale)
{
    extern __shared__ uint32_t sm[];
    const uint32_t smb = smem_u32(sm);

    const int tid  = threadIdx.x;
    const int lane = tid & 31;
    const int wid  = tid >> 5;
    const int g    = lane >> 2;       // 0..7
    const int t    = lane & 3;        // 0..3
    const int warpM = (wid >> 2) * 64;
    const int warpN = (wid & 3) * 32;

    const int m0 = blockIdx.y * 128, n0 = blockIdx.x * 128;
    const __half* Ap = A + blockIdx.z * aStride;
    const __half* Bp = B + blockIdx.z * bStride;

    // loader: thread covers rows r0 + {0,32,64,96}, fixed 16B (8-half) col kq
    const int r0 = tid >> 3;          // 0..31
    const int kq = tid & 7;

    // LDSM lane offsets (u32 units within operand)
    const int l15 = lane & 15, lhi = lane >> 4;
    int offA[4];
#pragma unroll
    for (int mt = 0; mt < 4; mt++)
        offA[mt] = (warpM + mt * 16 + l15) * SM_STRIDE + lhi * 4;
    const int sub = lane >> 3, l7 = lane & 7;
    int offB[2];
#pragma unroll
    for (int p = 0; p < 2; p++)
        offB[p] = (warpN + (2 * p + (sub >> 1)) * 8 + l7) * SM_STRIDE + (sub & 1) * 4;

    float acc[4][4][4] = {};

    auto fill = [&](int st, int k0) {
        uint32_t dA = smb + (uint32_t)(st * SM_STAGE + r0 * SM_STRIDE + kq * 4) * 4;
        uint32_t dB = dA + SM_OP * 4;
        const __half* sA = Ap + (size_t)(m0 + r0) * ldA + k0 + kq * 8;
        const __half* sB = Bp + (size_t)(n0 + r0) * ldB + k0 + kq * 8;
#pragma unroll
        for (int i = 0; i < 4; i++) {
            cpasync16(dA + (uint32_t)(32 * i * SM_STRIDE) * 4, sA + (size_t)(32 * i) * ldA);
            cpasync16(dB + (uint32_t)(32 * i * SM_STRIDE) * 4, sB + (size_t)(32 * i) * ldB);
        }
        asm volatile("cp.async.commit_group;");
    };

    const int nch = K >> 6;
    fill(0, 0);
    if (nch > 1) fill(1, 64);

    for (int c = 0; c < nch; c++) {
        const int s = c % NSTAGE;
        if (c + 1 < nch) asm volatile("cp.async.wait_group 1;");
        else             asm volatile("cp.async.wait_group 0;");
        __syncthreads();
        if (c + 2 < nch) fill((c + 2) % NSTAGE, (c + 2) * 64);

        const uint32_t stA = smb + (uint32_t)(s * SM_STAGE) * 4;
        const uint32_t stB = stA + SM_OP * 4;
#pragma unroll
        for (int kk = 0; kk < 4; kk++) {            // k16 step = 8 u32 cols
            uint32_t af[4][4], bf[2][4];
#pragma unroll
            for (int mt = 0; mt < 4; mt++)
                ldsm4(af[mt][0], af[mt][1], af[mt][2], af[mt][3],
                      stA + (uint32_t)(offA[mt] + kk * 8) * 4);
#pragma unroll
            for (int p = 0; p < 2; p++)
                ldsm4(bf[p][0], bf[p][1], bf[p][2], bf[p][3],
                      stB + (uint32_t)(offB[p] + kk * 8) * 4);
#pragma unroll
            for (int mt = 0; mt < 4; mt++)
#pragma unroll
                for (int nt = 0; nt < 4; nt++)
                    mma16(acc[mt][nt], af[mt][0], af[mt][1], af[mt][2], af[mt][3],
                          bf[nt >> 1][(nt & 1) * 2], bf[nt >> 1][(nt & 1) * 2 + 1]);
        }
    }

    // epilogue
#pragma unroll
    for (int mt = 0; mt < 4; mt++) {
        int row = m0 + warpM + mt * 16 + g;
        float b0 = 0.f, b1 = 0.f;
        if (HASBIAS) { b0 = bias[row]; b1 = bias[row + 8]; }
#pragma unroll
        for (int nt = 0; nt < 4; nt++) {
            int col = n0 + warpN + nt * 8 + 2 * t;
            float v0 = acc[mt][nt][0] * scale + b0;
            float v1 = acc[mt][nt][1] * scale + b0;
            float v2 = acc[mt][nt][2] * scale + b1;
            float v3 = acc[mt][nt][3] * scale + b1;
            if (OUTF32) {
                float* Cf = (float*)Cvoid + blockIdx.z * cStride;
                const float* Rp = resid + blockIdx.z * rStride;
                float2 r0v = *(const float2*)(Rp + (size_t)row * ldC + col);
                float2 r1v = *(const float2*)(Rp + (size_t)(row + 8) * ldC + col);
                v0 += r0v.x; v1 += r0v.y; v2 += r1v.x; v3 += r1v.y;
                *(float2*)(Cf + (size_t)row * ldC + col)       = make_float2(v0, v1);
                *(float2*)(Cf + (size_t)(row + 8) * ldC + col) = make_float2(v2, v3);
            } else {
                __half* Ch = (__half*)Cvoid + blockIdx.z * cStride;
                if (TRANS) {
                    Ch[(size_t)(col)     * ldC + row    ] = __float2half_rn(v0);
                    Ch[(size_t)(col + 1) * ldC + row    ] = __float2half_rn(v1);
                    Ch[(size_t)(col)     * ldC + row + 8] = __float2half_rn(v2);
                    Ch[(size_t)(col + 1) * ldC + row + 8] = __float2half_rn(v3);
                } else {
                    *(__half2*)(Ch + (size_t)row * ldC + col)       = __floats2half2_rn(v0, v1);
                    *(__half2*)(Ch + (size_t)(row + 8) * ldC + col) = __floats2half2_rn(v2, v3);
                }
            }
        }
    }
}

// ---------------------------------------------------------------------------
// Row softmax in place over last dim (4096), fp16 storage, fp32 math.
// ---------------------------------------------------------------------------
__global__ __launch_bounds__(256) void softmax_h_kernel(__half* __restrict__ S)
{
    __half2* p2 = (__half2*)(S + (size_t)blockIdx.x * HW);   // 2048 half2
    int tid = threadIdx.x;
    float2 v[8];
    float mx = -3.0e38f;
#pragma unroll
    for (int i = 0; i < 8; i++) {
        v[i] = __half22float2(p2[tid + i * 256]);
        mx = fmaxf(mx, fmaxf(v[i].x, v[i].y));
    }
    __shared__ float red[8];
#pragma unroll
    for (int o = 16; o > 0; o >>= 1) mx = fmaxf(mx, __shfl_xor_sync(0xffffffffu, mx, o));
    if ((tid & 31) == 0) red[tid >> 5] = mx;
    __syncthreads();
    mx = red[0];
#pragma unroll
    for (int w = 1; w < 8; w++) mx = fmaxf(mx, red[w]);

    float sum = 0.f;
#pragma unroll
    for (int i = 0; i < 8; i++) {
        v[i].x = __expf(v[i].x - mx); v[i].y = __expf(v[i].y - mx);
        sum += v[i].x + v[i].y;
    }
#pragma unroll
    for (int o = 16; o > 0; o >>= 1) sum += __shfl_xor_sync(0xffffffffu, sum, o);
    __syncthreads();
    if ((tid & 31) == 0) red[tid >> 5] = sum;
    __syncthreads();
    sum = 0.f;
#pragma unroll
    for (int w = 0; w < 8; w++) sum += red[w];
    float inv = 1.f / sum;
#pragma unroll
    for (int i = 0; i < 8; i++)
        p2[tid + i * 256] = __floats2half2_rn(v[i].x * inv, v[i].y * inv);
}

// ---------------------------------------------------------------------------
extern "C" void kernel_launch(void* const* d_in, const int* in_sizes, int n_in,
                              void* d_out, int out_size)
{
    const float* x     = (const float*)d_in[0];
    const float* gamma = (const float*)d_in[1];
    const float* beta  = (const float*)d_in[2];
    const float* wq    = (const float*)d_in[3];
    const float* bq    = (const float*)d_in[4];
    const float* wk    = (const float*)d_in[5];
    const float* bk    = (const float*)d_in[6];
    const float* wv    = (const float*)d_in[7];
    const float* bv    = (const float*)d_in[8];
    const float* wo    = (const float*)d_in[9];
    const float* bo    = (const float*)d_in[10];
    float* out = (float*)d_out;

    __half *pwh, *pht, *pq, *pk, *pv, *po, *ps;
    cudaGetSymbolAddress((void**)&pwh, g_wh);
    cudaGetSymbolAddress((void**)&pht, g_ht);
    cudaGetSymbolAddress((void**)&pq,  g_q);
    cudaGetSymbolAddress((void**)&pk,  g_k);
    cudaGetSymbolAddress((void**)&pv,  g_v);
    cudaGetSymbolAddress((void**)&po,  g_o);
    cudaGetSymbolAddress((void**)&ps,  g_s);

    cudaFuncSetAttribute(mma_gemm<true,  true,  false>, cudaFuncAttributeMaxDynamicSharedMemorySize, SMEM_BYTES);
    cudaFuncSetAttribute(mma_gemm<false, true,  false>, cudaFuncAttributeMaxDynamicSharedMemorySize, SMEM_BYTES);
    cudaFuncSetAttribute(mma_gemm<false, false, false>, cudaFuncAttributeMaxDynamicSharedMemorySize, SMEM_BYTES);
    cudaFuncSetAttribute(mma_gemm<true,  false, false>, cudaFuncAttributeMaxDynamicSharedMemorySize, SMEM_BYTES);
    cudaFuncSetAttribute(mma_gemm<false, true,  true >, cudaFuncAttributeMaxDynamicSharedMemorySize, SMEM_BYTES);

    // weights -> fp16 (one launch)
    f2h4_kernel<<<1024, 256>>>(wq, wk, wv, wo, pwh);

    // GroupNorm -> H^T[n][c] fp16
    groupnorm_t_kernel<<<NB * NG, 512>>>(x, gamma, beta, pht);

    dim3 gP(HW / 128, CH / 128, NB);   // proj GEMMs: M=512, N=4096
    dim3 gS(HW / 128, HW / 128, NB);   // scores: M=N=4096

    // Q^T = (Wq . H)^T, transposed epilogue
    mma_gemm<true, true, false><<<gP, 256, SMEM_BYTES>>>(pwh + 0 * CH * CH, CH, 0,
        pht, CH, CHW, pq, CH, CHW, bq, nullptr, 0, CH, 1.f);
    // K^T
    mma_gemm<true, true, false><<<gP, 256, SMEM_BYTES>>>(pwh + 1 * CH * CH, CH, 0,
        pht, CH, CHW, pk, CH, CHW, bk, nullptr, 0, CH, 1.f);
    // V natural [d][n]
    mma_gemm<false, true, false><<<gP, 256, SMEM_BYTES>>>(pwh + 2 * CH * CH, CH, 0,
        pht, CH, CHW, pv, HW, CHW, bv, nullptr, 0, CH, 1.f);
    // S[n][m] = scale * Q . K^T
    mma_gemm<false, false, false><<<gS, 256, SMEM_BYTES>>>(pq, CH, CHW, pk, CH, CHW,
        ps, HW, SS, nullptr, nullptr, 0, CH, 0.04419417382415922f);
    softmax_h_kernel<<<NB * HW, 256>>>(ps);

    // O^T[n][c]: A = V[c][m], B = attn[n][m], k = m; transposed write
    mma_gemm<true, false, false><<<gP, 256, SMEM_BYTES>>>(pv, HW, CHW, ps, HW, SS,
        po, CH, CHW, nullptr, nullptr, 0, HW, 1.f);
    // out[d][n] = Wo . O + bo + x  (fp32 out + residual)
    mma_gemm<false, true, true><<<gP, 256, SMEM_BYTES>>>(pwh + 3 * CH * CH, CH, 0,
        po, CH, CHW, out, HW, CHW, bo, x, CHW, CH, 1.f);
}

// round 17
// speedup vs baseline: 3.0004x; 1.0082x over previous
#include <cuda_runtime.h>
#include <cuda_fp16.h>
#include <cstdint>

#define NB 4
#define CH 512
#define HW 4096
#define NG 32
#define CPG 16
#define CHW ((long long)CH * HW)   // 2097152
#define SS  ((long long)HW * HW)   // 16777216

// smem geometry (uint32 units): 128 rows x (32 k-u32 + 4 pad) -> stride 36
#define SM_STRIDE 36
#define SM_OP     (128 * SM_STRIDE)       // 4608 u32 per operand
#define SM_STAGE  (2 * SM_OP)             // A + B per stage
#define NSTAGE    3
#define SMEM_BYTES (NSTAGE * SM_STAGE * 4)   // 110592 B, triple buffered

// Scratch (static device globals: allocation-free per harness rules)
static __device__ __half g_wh[4 * CH * CH];                // fp16 weights q,k,v,o
static __device__ __half g_ht[NB * CH * HW];               // H^T  [n][c]
static __device__ __half g_q [NB * CH * HW];               // Q^T  [n][c]
static __device__ __half g_k [NB * CH * HW];               // K^T  [m][c]
static __device__ __half g_v [NB * CH * HW];               // V    [c][m]
static __device__ __half g_o [NB * CH * HW];               // O^T  [n][c]
static __device__ __half g_s [(size_t)NB * HW * HW];       // S    [n][m]

// ---------------------------------------------------------------------------
// helpers
// ---------------------------------------------------------------------------
__device__ __forceinline__ void mma16(float* c, uint32_t a0, uint32_t a1,
                                      uint32_t a2, uint32_t a3,
                                      uint32_t b0, uint32_t b1) {
    asm volatile(
        "mma.sync.aligned.m16n8k16.row.col.f32.f16.f16.f32 "
        "{%0,%1,%2,%3}, {%4,%5,%6,%7}, {%8,%9}, {%0,%1,%2,%3};"
        : "+f"(c[0]), "+f"(c[1]), "+f"(c[2]), "+f"(c[3])
        : "r"(a0), "r"(a1), "r"(a2), "r"(a3), "r"(b0), "r"(b1));
}

__device__ __forceinline__ void ldsm4(uint32_t& r0, uint32_t& r1,
                                      uint32_t& r2, uint32_t& r3, uint32_t a) {
    asm volatile("ldmatrix.sync.aligned.m8n8.x4.shared.b16 {%0,%1,%2,%3}, [%4];"
                 : "=r"(r0), "=r"(r1), "=r"(r2), "=r"(r3) : "r"(a));
}

__device__ __forceinline__ void cpasync16(uint32_t dst, const void* src) {
    asm volatile("cp.async.cg.shared.global [%0], [%1], 16;" :: "r"(dst), "l"(src));
}

__device__ __forceinline__ uint32_t smem_u32(const void* p) {
    uint32_t a;
    asm("{ .reg .u64 t; cvta.to.shared.u64 t, %1; cvt.u32.u64 %0, t; }" : "=r"(a) : "l"(p));
    return a;
}

// ---------------------------------------------------------------------------
// fp32 -> fp16 conversion of all 4 weight matrices in one launch. grid 1024.
// ---------------------------------------------------------------------------
__global__ __launch_bounds__(256) void f2h4_kernel(
    const float* __restrict__ w0, const float* __restrict__ w1,
    const float* __restrict__ w2, const float* __restrict__ w3,
    __half* __restrict__ dst)
{
    int which = blockIdx.x >> 8;                  // 0..3
    int i = (blockIdx.x & 255) * 256 + threadIdx.x;  // 65536 float4s per weight
    const float* src = which == 0 ? w0 : which == 1 ? w1 : which == 2 ? w2 : w3;
    float4 v = ((const float4*)src)[i];
    __half2* d2 = (__half2*)(dst + (size_t)which * CH * CH);
    d2[2 * i]     = __floats2half2_rn(v.x, v.y);
    d2[2 * i + 1] = __floats2half2_rn(v.z, v.w);
}

// ---------------------------------------------------------------------------
// GroupNorm -> transposed fp16 output H^T[n][c].
// ---------------------------------------------------------------------------
__global__ __launch_bounds__(512) void groupnorm_t_kernel(
    const float* __restrict__ x, const float* __restrict__ gamma,
    const float* __restrict__ beta, __half* __restrict__ ht)
{
    int b = blockIdx.x / NG, grp = blockIdx.x % NG;
    size_t base = ((size_t)b * CH + (size_t)grp * CPG) * HW;
    const float4* x4 = (const float4*)(x + base);
    const int n4 = CPG * HW / 4;  // 16384

    float s = 0.f, ss = 0.f;
    for (int i = threadIdx.x; i < n4; i += blockDim.x) {
        float4 v = x4[i];
        s  += v.x + v.y + v.z + v.w;
        ss += v.x * v.x + v.y * v.y + v.z * v.z + v.w * v.w;
    }
    __shared__ float shs[16], shss[16];
#pragma unroll
    for (int o = 16; o > 0; o >>= 1) {
        s  += __shfl_xor_sync(0xffffffffu, s, o);
        ss += __shfl_xor_sync(0xffffffffu, ss, o);
    }
    int wid = threadIdx.x >> 5, lid = threadIdx.x & 31;
    if (lid == 0) { shs[wid] = s; shss[wid] = ss; }
    __syncthreads();
    if (threadIdx.x == 0) {
        float ts = 0.f, tss = 0.f;
#pragma unroll
        for (int w = 0; w < 16; w++) { ts += shs[w]; tss += shss[w]; }
        shs[0] = ts; shss[0] = tss;
    }
    __syncthreads();
    const float invn = 1.f / (float)(CPG * HW);
    float mean = shs[0] * invn;
    float var  = shss[0] * invn - mean * mean;
    float rstd = rsqrtf(var + 1e-5f);

    int ch  = threadIdx.x >> 5;        // 0..15
    int nl  = threadIdx.x & 31;        // 0..31
    float ga = gamma[grp * CPG + ch] * rstd;
    float be = beta [grp * CPG + ch] - mean * ga;

    __shared__ float sm[16 * 132];
    __half* htp = ht + (size_t)b * CHW;

    for (int tile = 0; tile < HW / 128; tile++) {
        float4 v = x4[ch * (HW / 4) + tile * 32 + nl];
        v.x = v.x * ga + be; v.y = v.y * ga + be;
        v.z = v.z * ga + be; v.w = v.w * ga + be;
        *(float4*)&sm[ch * 132 + nl * 4] = v;
        __syncthreads();
        int i  = threadIdx.x >> 2;     // 0..127
        int c4 = threadIdx.x & 3;      // 0..3
        float4 w;
        w.x = sm[(c4 * 4 + 0) * 132 + i];
        w.y = sm[(c4 * 4 + 1) * 132 + i];
        w.z = sm[(c4 * 4 + 2) * 132 + i];
        w.w = sm[(c4 * 4 + 3) * 132 + i];
        __half2* dst = (__half2*)(htp + (size_t)(tile * 128 + i) * CH + grp * CPG + c4 * 4);
        dst[0] = __floats2half2_rn(w.x, w.y);
        dst[1] = __floats2half2_rn(w.z, w.w);
        __syncthreads();
    }
}

// ---------------------------------------------------------------------------
// Unified fp16 mma GEMM (fp32 accum), 3-stage cp.async ring, LDSM frags.
//   C[m][n] = scale * sum_k A[m][k] * B[n][k]  (operands k-contiguous fp16)
//   128x128 tile, BK=64 halves, 256 threads (8 warps, 64x32 warp tiles).
//   All outputs written in NATURAL layout (transposes done by operand swap
//   at the call site: C^T = B (.) A). BIAS: 0 none, 1 bias[row], 2 bias[col].
// ---------------------------------------------------------------------------
template<int BIAS, bool OUTF32>
__global__ __launch_bounds__(256, 2) void mma_gemm(
    const __half* __restrict__ A, int ldA, long long aStride,
    const __half* __restrict__ B, int ldB, long long bStride,
    void* __restrict__ Cvoid, int ldC, long long cStride,
    const float* __restrict__ bias,
    const float* __restrict__ resid, long long rStride,
    int K, float scale)
{
    extern __shared__ uint32_t sm[];
    const uint32_t smb = smem_u32(sm);

    const int tid  = threadIdx.x;
    const int lane = tid & 31;
    const int wid  = tid >> 5;
    const int g    = lane >> 2;       // 0..7
    const int t    = lane & 3;        // 0..3
    const int warpM = (wid >> 2) * 64;
    const int warpN = (wid & 3) * 32;

    const int m0 = blockIdx.y * 128, n0 = blockIdx.x * 128;
    const __half* Ap = A + blockIdx.z * aStride;
    const __half* Bp = B + blockIdx.z * bStride;

    // loader: thread covers rows r0 + {0,32,64,96}, fixed 16B (8-half) col kq
    const int r0 = tid >> 3;          // 0..31
    const int kq = tid & 7;

    // LDSM lane offsets (u32 units within operand)
    const int l15 = lane & 15, lhi = lane >> 4;
    int offA[4];
#pragma unroll
    for (int mt = 0; mt < 4; mt++)
        offA[mt] = (warpM + mt * 16 + l15) * SM_STRIDE + lhi * 4;
    const int sub = lane >> 3, l7 = lane & 7;
    int offB[2];
#pragma unroll
    for (int p = 0; p < 2; p++)
        offB[p] = (warpN + (2 * p + (sub >> 1)) * 8 + l7) * SM_STRIDE + (sub & 1) * 4;

    float acc[4][4][4] = {};

    auto fill = [&](int st, int k0) {
        uint32_t dA = smb + (uint32_t)(st * SM_STAGE + r0 * SM_STRIDE + kq * 4) * 4;
        uint32_t dB = dA + SM_OP * 4;
        const __half* sA = Ap + (size_t)(m0 + r0) * ldA + k0 + kq * 8;
        const __half* sB = Bp + (size_t)(n0 + r0) * ldB + k0 + kq * 8;
#pragma unroll
        for (int i = 0; i < 4; i++) {
            cpasync16(dA + (uint32_t)(32 * i * SM_STRIDE) * 4, sA + (size_t)(32 * i) * ldA);
            cpasync16(dB + (uint32_t)(32 * i * SM_STRIDE) * 4, sB + (size_t)(32 * i) * ldB);
        }
        asm volatile("cp.async.commit_group;");
    };

    const int nch = K >> 6;
    fill(0, 0);
    if (nch > 1) fill(1, 64);

    for (int c = 0; c < nch; c++) {
        const int s = c % NSTAGE;
        if (c + 1 < nch) asm volatile("cp.async.wait_group 1;");
        else             asm volatile("cp.async.wait_group 0;");
        __syncthreads();
        if (c + 2 < nch) fill((c + 2) % NSTAGE, (c + 2) * 64);

        const uint32_t stA = smb + (uint32_t)(s * SM_STAGE) * 4;
        const uint32_t stB = stA + SM_OP * 4;
#pragma unroll
        for (int kk = 0; kk < 4; kk++) {            // k16 step = 8 u32 cols
            uint32_t af[4][4], bf[2][4];
#pragma unroll
            for (int mt = 0; mt < 4; mt++)
                ldsm4(af[mt][0], af[mt][1], af[mt][2], af[mt][3],
                      stA + (uint32_t)(offA[mt] + kk * 8) * 4);
#pragma unroll
            for (int p = 0; p < 2; p++)
                ldsm4(bf[p][0], bf[p][1], bf[p][2], bf[p][3],
                      stB + (uint32_t)(offB[p] + kk * 8) * 4);
#pragma unroll
            for (int mt = 0; mt < 4; mt++)
#pragma unroll
                for (int nt = 0; nt < 4; nt++)
                    mma16(acc[mt][nt], af[mt][0], af[mt][1], af[mt][2], af[mt][3],
                          bf[nt >> 1][(nt & 1) * 2], bf[nt >> 1][(nt & 1) * 2 + 1]);
        }
    }

    // epilogue (natural layout, coalesced stores)
#pragma unroll
    for (int mt = 0; mt < 4; mt++) {
        int row = m0 + warpM + mt * 16 + g;
        float br0 = 0.f, br1 = 0.f;
        if (BIAS == 1) { br0 = bias[row]; br1 = bias[row + 8]; }
#pragma unroll
        for (int nt = 0; nt < 4; nt++) {
            int col = n0 + warpN + nt * 8 + 2 * t;
            float bc0 = 0.f, bc1 = 0.f;
            if (BIAS == 2) { bc0 = bias[col]; bc1 = bias[col + 1]; }
            float v0 = acc[mt][nt][0] * scale + br0 + bc0;
            float v1 = acc[mt][nt][1] * scale + br0 + bc1;
            float v2 = acc[mt][nt][2] * scale + br1 + bc0;
            float v3 = acc[mt][nt][3] * scale + br1 + bc1;
            if (OUTF32) {
                float* Cf = (float*)Cvoid + blockIdx.z * cStride;
                const float* Rp = resid + blockIdx.z * rStride;
                float2 r0v = *(const float2*)(Rp + (size_t)row * ldC + col);
                float2 r1v = *(const float2*)(Rp + (size_t)(row + 8) * ldC + col);
                v0 += r0v.x; v1 += r0v.y; v2 += r1v.x; v3 += r1v.y;
                *(float2*)(Cf + (size_t)row * ldC + col)       = make_float2(v0, v1);
                *(float2*)(Cf + (size_t)(row + 8) * ldC + col) = make_float2(v2, v3);
            } else {
                __half* Ch = (__half*)Cvoid + blockIdx.z * cStride;
                *(__half2*)(Ch + (size_t)row * ldC + col)       = __floats2half2_rn(v0, v1);
                *(__half2*)(Ch + (size_t)(row + 8) * ldC + col) = __floats2half2_rn(v2, v3);
            }
        }
    }
}

// ---------------------------------------------------------------------------
// Row softmax in place over last dim (4096), fp16 storage, fp32 math.
// uint4 (16B) vectorized loads/stores: 2 per thread.
// ---------------------------------------------------------------------------
__global__ __launch_bounds__(256) void softmax_h_kernel(__half* __restrict__ S)
{
    uint4* p4 = (uint4*)(S + (size_t)blockIdx.x * HW);   // 512 uint4 per row
    int tid = threadIdx.x;
    uint4 raw[2];
    float2 v[2][4];
    float mx = -3.0e38f;
#pragma unroll
    for (int i = 0; i < 2; i++) {
        raw[i] = p4[tid + i * 256];
        const __half2* h = (const __half2*)&raw[i];
#pragma unroll
        for (int j = 0; j < 4; j++) {
            v[i][j] = __half22float2(h[j]);
            mx = fmaxf(mx, fmaxf(v[i][j].x, v[i][j].y));
        }
    }
    __shared__ float red[8];
#pragma unroll
    for (int o = 16; o > 0; o >>= 1) mx = fmaxf(mx, __shfl_xor_sync(0xffffffffu, mx, o));
    if ((tid & 31) == 0) red[tid >> 5] = mx;
    __syncthreads();
    mx = red[0];
#pragma unroll
    for (int w = 1; w < 8; w++) mx = fmaxf(mx, red[w]);

    float sum = 0.f;
#pragma unroll
    for (int i = 0; i < 2; i++)
#pragma unroll
        for (int j = 0; j < 4; j++) {
            v[i][j].x = __expf(v[i][j].x - mx);
            v[i][j].y = __expf(v[i][j].y - mx);
            sum += v[i][j].x + v[i][j].y;
        }
#pragma unroll
    for (int o = 16; o > 0; o >>= 1) sum += __shfl_xor_sync(0xffffffffu, sum, o);
    __syncthreads();
    if ((tid & 31) == 0) red[tid >> 5] = sum;
    __syncthreads();
    sum = 0.f;
#pragma unroll
    for (int w = 0; w < 8; w++) sum += red[w];
    float inv = 1.f / sum;
#pragma unroll
    for (int i = 0; i < 2; i++) {
        uint4 o4;
        __half2* h = (__half2*)&o4;
#pragma unroll
        for (int j = 0; j < 4; j++)
            h[j] = __floats2half2_rn(v[i][j].x * inv, v[i][j].y * inv);
        p4[tid + i * 256] = o4;
    }
}

// ---------------------------------------------------------------------------
extern "C" void kernel_launch(void* const* d_in, const int* in_sizes, int n_in,
                              void* d_out, int out_size)
{
    const float* x     = (const float*)d_in[0];
    const float* gamma = (const float*)d_in[1];
    const float* beta  = (const float*)d_in[2];
    const float* wq    = (const float*)d_in[3];
    const float* bq    = (const float*)d_in[4];
    const float* wk    = (const float*)d_in[5];
    const float* bk    = (const float*)d_in[6];
    const float* wv    = (const float*)d_in[7];
    const float* bv    = (const float*)d_in[8];
    const float* wo    = (const float*)d_in[9];
    const float* bo    = (const float*)d_in[10];
    float* out = (float*)d_out;

    __half *pwh, *pht, *pq, *pk, *pv, *po, *ps;
    cudaGetSymbolAddress((void**)&pwh, g_wh);
    cudaGetSymbolAddress((void**)&pht, g_ht);
    cudaGetSymbolAddress((void**)&pq,  g_q);
    cudaGetSymbolAddress((void**)&pk,  g_k);
    cudaGetSymbolAddress((void**)&pv,  g_v);
    cudaGetSymbolAddress((void**)&po,  g_o);
    cudaGetSymbolAddress((void**)&ps,  g_s);

    cudaFuncSetAttribute(mma_gemm<2, false>, cudaFuncAttributeMaxDynamicSharedMemorySize, SMEM_BYTES);
    cudaFuncSetAttribute(mma_gemm<1, false>, cudaFuncAttributeMaxDynamicSharedMemorySize, SMEM_BYTES);
    cudaFuncSetAttribute(mma_gemm<0, false>, cudaFuncAttributeMaxDynamicSharedMemorySize, SMEM_BYTES);
    cudaFuncSetAttribute(mma_gemm<1, true >, cudaFuncAttributeMaxDynamicSharedMemorySize, SMEM_BYTES);

    // weights -> fp16 (one launch)
    f2h4_kernel<<<1024, 256>>>(wq, wk, wv, wo, pwh);

    // GroupNorm -> H^T[n][c] fp16
    groupnorm_t_kernel<<<NB * NG, 512>>>(x, gamma, beta, pht);

    // Q^T[n][d] = sum_k Ht[n][k] Wq[d][k] + bq[d]  (operand swap, bias-col)
    dim3 gQ(CH / 128, HW / 128, NB);   // 4 x 32 x 4
    mma_gemm<2, false><<<gQ, 256, SMEM_BYTES>>>(pht, CH, CHW, pwh + 0 * CH * CH, CH, 0,
        pq, CH, CHW, bq, nullptr, 0, CH, 1.f);
    // K^T[m][d]
    mma_gemm<2, false><<<gQ, 256, SMEM_BYTES>>>(pht, CH, CHW, pwh + 1 * CH * CH, CH, 0,
        pk, CH, CHW, bk, nullptr, 0, CH, 1.f);
    // V[c][m] = sum_k Wv[c][k] Ht[m][k] + bv[c]  (natural, bias-row)
    dim3 gV(HW / 128, CH / 128, NB);   // 32 x 4 x 4
    mma_gemm<1, false><<<gV, 256, SMEM_BYTES>>>(pwh + 2 * CH * CH, CH, 0, pht, CH, CHW,
        pv, HW, CHW, bv, nullptr, 0, CH, 1.f);
    // S[n][m] = scale * Q^T . K^T
    dim3 gS(HW / 128, HW / 128, NB);   // 32 x 32 x 4
    mma_gemm<0, false><<<gS, 256, SMEM_BYTES>>>(pq, CH, CHW, pk, CH, CHW,
        ps, HW, SS, nullptr, nullptr, 0, CH, 0.04419417382415922f);

    softmax_h_kernel<<<NB * HW, 256>>>(ps);

    // O^T[n][c] = sum_m S[n][m] V[c][m]  (operand swap, natural write)
    mma_gemm<0, false><<<gQ, 256, SMEM_BYTES>>>(ps, HW, SS, pv, HW, CHW,
        po, CH, CHW, nullptr, nullptr, 0, HW, 1.f);
    // out[d][n] = sum_c Wo[d][c] Ot[n][c] + bo[d] + x  (fp32 + residual)
    mma_gemm<1, true><<<gV, 256, SMEM_BYTES>>>(pwh + 3 * CH * CH, CH, 0, po, CH, CHW,
        out, HW, CHW, bo, x, CHW, CH, 1.f);
}